// round 2
// baseline (speedup 1.0000x reference)
#include <cuda_runtime.h>

#define NN 100000
#define EE 1600000
#define HD 64

// ---------------- scratch (device globals; allocation-free rule) ----------------
__device__ float g_e[(size_t)EE * HD];        // encoded edge features (410 MB)
__device__ float g_h[(size_t)NN * HD];        // node state
__device__ float g_z[(size_t)NN * HD];        // pre-norm conv input
__device__ float g_S[(size_t)NN * 2 * HD];    // per-node {ex, msg*ex} per channel

// ---------------- encoder: Y[M,64] = X[M,64] @ W[64,64] + b ----------------
__global__ void enc_kernel(const float* __restrict__ X, const float* __restrict__ W,
                           const float* __restrict__ b, float* __restrict__ Y, int M)
{
    __shared__ float Ws[64 * 64];
    __shared__ float bs[64];
    for (int i = threadIdx.x; i < 64 * 64; i += blockDim.x) Ws[i] = W[i];
    if (threadIdx.x < 64) bs[threadIdx.x] = b[threadIdx.x];
    __syncthreads();

    int row = blockIdx.x * blockDim.x + threadIdx.x;
    if (row >= M) return;

    float xr[64];
    const float4* xp = reinterpret_cast<const float4*>(X + (size_t)row * 64);
#pragma unroll
    for (int i = 0; i < 16; i++) {
        float4 v = xp[i];
        xr[4 * i + 0] = v.x; xr[4 * i + 1] = v.y;
        xr[4 * i + 2] = v.z; xr[4 * i + 3] = v.w;
    }
    float4* yp = reinterpret_cast<float4*>(Y + (size_t)row * 64);
#pragma unroll
    for (int jc = 0; jc < 4; jc++) {
        float acc[16];
#pragma unroll
        for (int q = 0; q < 16; q++) acc[q] = bs[jc * 16 + q];
#pragma unroll
        for (int k = 0; k < 64; k++) {
            float xv = xr[k];
            const float4* wr = reinterpret_cast<const float4*>(Ws + k * 64 + jc * 16);
#pragma unroll
            for (int u = 0; u < 4; u++) {
                float4 wv = wr[u];
                acc[4 * u + 0] += xv * wv.x;
                acc[4 * u + 1] += xv * wv.y;
                acc[4 * u + 2] += xv * wv.z;
                acc[4 * u + 3] += xv * wv.w;
            }
        }
#pragma unroll
        for (int u = 0; u < 4; u++)
            yp[jc * 4 + u] = make_float4(acc[4 * u], acc[4 * u + 1], acc[4 * u + 2], acc[4 * u + 3]);
    }
}

// ---------------- zero the softmax accumulators ----------------
__global__ void zero_kernel()
{
    size_t i = (size_t)blockIdx.x * blockDim.x + threadIdx.x;
    float4* p = reinterpret_cast<float4*>(g_S);
    if (i < (size_t)NN * 32) p[i] = make_float4(0.f, 0.f, 0.f, 0.f);
}

// ---------------- LayerNorm(64) + ReLU : out = relu(LN(h, g, b)) ----------------
__global__ void lnrelu_kernel(const float* __restrict__ hin, const float* __restrict__ g,
                              const float* __restrict__ b, float* __restrict__ out)
{
    int gt = blockIdx.x * blockDim.x + threadIdx.x;
    int node = gt >> 5;
    if (node >= NN) return;
    int lane = threadIdx.x & 31;

    float2 v = reinterpret_cast<const float2*>(hin + (size_t)node * 64)[lane];
    float s = v.x + v.y;
#pragma unroll
    for (int o = 16; o; o >>= 1) s += __shfl_xor_sync(0xffffffffu, s, o);
    float mu = s * (1.f / 64.f);
    float dx = v.x - mu, dy = v.y - mu;
    float q = dx * dx + dy * dy;
#pragma unroll
    for (int o = 16; o; o >>= 1) q += __shfl_xor_sync(0xffffffffu, q, o);
    float rstd = rsqrtf(q * (1.f / 64.f) + 1e-5f);

    float2 gg = reinterpret_cast<const float2*>(g)[lane];
    float2 bb = reinterpret_cast<const float2*>(b)[lane];
    float2 r;
    r.x = fmaxf(dx * rstd * gg.x + bb.x, 0.f);
    r.y = fmaxf(dy * rstd * gg.y + bb.y, 0.f);
    reinterpret_cast<float2*>(out + (size_t)node * 64)[lane] = r;
}

// ---------------- edge pass: one warp per edge ----------------
// msg = relu(z[src]+e)+eps ; ex = exp(msg*t) ; S[dst] += {ex, msg*ex} (v4 reductions)
__global__ void edge_kernel(const float* __restrict__ zin, const int* __restrict__ ei,
                            const float* __restrict__ tp)
{
    int gt = blockIdx.x * blockDim.x + threadIdx.x;
    int w = gt >> 5;
    if (w >= EE) return;
    int lane = threadIdx.x & 31;

    int src = __ldg(ei + w);
    int dst = __ldg(ei + EE + w);
    float t = __ldg(tp);

    float2 ev = reinterpret_cast<const float2*>(g_e + (size_t)w * 64)[lane];
    float2 hv = reinterpret_cast<const float2*>(zin + (size_t)src * 64)[lane];

    float m0 = fmaxf(hv.x + ev.x, 0.f) + 1e-7f;   // msg (channel 2*lane)
    float m1 = fmaxf(hv.y + ev.y, 0.f) + 1e-7f;   // msg (channel 2*lane+1)
    float e0 = __expf(m0 * t);
    float e1 = __expf(m1 * t);

    float* p = g_S + (size_t)dst * 128 + lane * 4;
    asm volatile("red.global.add.v4.f32 [%0], {%1, %2, %3, %4};"
                 :: "l"(p), "f"(e0), "f"(m0 * e0), "f"(e1), "f"(m1 * e1)
                 : "memory");
}

// ---------------- fused node pass: one warp per node ----------------
// out = conv_in + S2/(S1+1e-16); z1 = relu(LN(out@W1+b1)); y = z1@W2+b2;
// h_out = (residual ? h_in + y : y)
__global__ void node_kernel(const float* __restrict__ conv_in,
                            const float* __restrict__ h_in,
                            float* __restrict__ h_out,
                            const float* __restrict__ w1,   // [64][128]
                            const float* __restrict__ b1,   // [128]
                            const float* __restrict__ g1,   // [128]
                            const float* __restrict__ bb1,  // [128]
                            const float* __restrict__ w2,   // [128][64]
                            const float* __restrict__ b2,   // [64]
                            int add_residual)
{
    extern __shared__ float sm[];
    float* w1s  = sm;                 // 8192
    float* w2s  = sm + 8192;          // 8192
    float* b1s  = sm + 16384;         // 128
    float* g1s  = b1s + 128;          // 128
    float* bb1s = g1s + 128;          // 128
    float* b2s  = bb1s + 128;         // 64

    int tid = threadIdx.x;
    for (int i = tid; i < 64 * 128; i += blockDim.x) w1s[i] = w1[i];
    for (int i = tid; i < 128 * 64; i += blockDim.x) w2s[i] = w2[i];
    if (tid < 128) { b1s[tid] = b1[tid]; g1s[tid] = g1[tid]; bb1s[tid] = bb1[tid]; }
    if (tid < 64)  b2s[tid] = b2[tid];
    __syncthreads();

    int node = (blockIdx.x * blockDim.x + tid) >> 5;
    if (node >= NN) return;
    int lane = tid & 31;

    // aggregation + root skip (channels 2*lane, 2*lane+1)
    float4 s  = *reinterpret_cast<const float4*>(g_S + (size_t)node * 128 + lane * 4);
    float2 ci = *reinterpret_cast<const float2*>(conv_in + (size_t)node * 64 + lane * 2);
    float o0 = ci.x + s.y / (s.x + 1e-16f);
    float o1 = ci.y + s.w / (s.z + 1e-16f);

    // matvec 1: z1[j], j = 4*lane+q
    float4 z1 = *reinterpret_cast<const float4*>(b1s + 4 * lane);
#pragma unroll
    for (int l = 0; l < 32; l++) {
        float a0 = __shfl_sync(0xffffffffu, o0, l);   // out channel 2*l
        float a1 = __shfl_sync(0xffffffffu, o1, l);   // out channel 2*l+1
        float4 wa = *reinterpret_cast<const float4*>(w1s + (2 * l) * 128 + 4 * lane);
        float4 wb = *reinterpret_cast<const float4*>(w1s + (2 * l + 1) * 128 + 4 * lane);
        z1.x += a0 * wa.x + a1 * wb.x;
        z1.y += a0 * wa.y + a1 * wb.y;
        z1.z += a0 * wa.z + a1 * wb.z;
        z1.w += a0 * wa.w + a1 * wb.w;
    }

    // LayerNorm over 128 + ReLU
    float ssum = z1.x + z1.y + z1.z + z1.w;
#pragma unroll
    for (int o = 16; o; o >>= 1) ssum += __shfl_xor_sync(0xffffffffu, ssum, o);
    float mu = ssum * (1.f / 128.f);
    float dx = z1.x - mu, dy = z1.y - mu, dz = z1.z - mu, dw = z1.w - mu;
    float sq = dx * dx + dy * dy + dz * dz + dw * dw;
#pragma unroll
    for (int o = 16; o; o >>= 1) sq += __shfl_xor_sync(0xffffffffu, sq, o);
    float rstd = rsqrtf(sq * (1.f / 128.f) + 1e-5f);
    float4 gv = *reinterpret_cast<const float4*>(g1s + 4 * lane);
    float4 bv = *reinterpret_cast<const float4*>(bb1s + 4 * lane);
    z1.x = fmaxf(dx * rstd * gv.x + bv.x, 0.f);
    z1.y = fmaxf(dy * rstd * gv.y + bv.y, 0.f);
    z1.z = fmaxf(dz * rstd * gv.z + bv.z, 0.f);
    z1.w = fmaxf(dw * rstd * gv.w + bv.w, 0.f);

    // matvec 2: y channels 2*lane, 2*lane+1
    float2 b2v = *reinterpret_cast<const float2*>(b2s + 2 * lane);
    float y0 = b2v.x, y1 = b2v.y;
#pragma unroll
    for (int l = 0; l < 32; l++) {
        float v0 = __shfl_sync(0xffffffffu, z1.x, l);  // j = 4*l
        float v1 = __shfl_sync(0xffffffffu, z1.y, l);  // j = 4*l+1
        float v2 = __shfl_sync(0xffffffffu, z1.z, l);  // j = 4*l+2
        float v3 = __shfl_sync(0xffffffffu, z1.w, l);  // j = 4*l+3
        float2 wa = *reinterpret_cast<const float2*>(w2s + (4 * l + 0) * 64 + 2 * lane);
        float2 wb = *reinterpret_cast<const float2*>(w2s + (4 * l + 1) * 64 + 2 * lane);
        float2 wc = *reinterpret_cast<const float2*>(w2s + (4 * l + 2) * 64 + 2 * lane);
        float2 wd = *reinterpret_cast<const float2*>(w2s + (4 * l + 3) * 64 + 2 * lane);
        y0 += v0 * wa.x + v1 * wb.x + v2 * wc.x + v3 * wd.x;
        y1 += v0 * wa.y + v1 * wb.y + v2 * wc.y + v3 * wd.y;
    }

    float2 r;
    if (add_residual) {
        float2 hv = *reinterpret_cast<const float2*>(h_in + (size_t)node * 64 + 2 * lane);
        r.x = hv.x + y0; r.y = hv.y + y1;
    } else {
        r.x = y0; r.y = y1;
    }
    *reinterpret_cast<float2*>(h_out + (size_t)node * 64 + 2 * lane) = r;
}

// ---------------- launch ----------------
extern "C" void kernel_launch(void* const* d_in, const int* in_sizes, int n_in,
                              void* d_out, int out_size)
{
    const float* x   = (const float*)d_in[0];
    const int*   ei  = (const int*)  d_in[1];
    const float* ea  = (const float*)d_in[2];
    const float* enw = (const float*)d_in[3];
    const float* enb = (const float*)d_in[4];
    const float* eew = (const float*)d_in[5];
    const float* eeb = (const float*)d_in[6];
    const float* lng = (const float*)d_in[7];
    const float* lnb = (const float*)d_in[8];
    const float* w1  = (const float*)d_in[9];
    const float* b1  = (const float*)d_in[10];
    const float* mg  = (const float*)d_in[11];
    const float* mb  = (const float*)d_in[12];
    const float* w2  = (const float*)d_in[13];
    const float* b2  = (const float*)d_in[14];
    const float* t   = (const float*)d_in[15];
    float* out = (float*)d_out;

    float *gh, *gz, *ge;
    cudaGetSymbolAddress((void**)&gh, g_h);
    cudaGetSymbolAddress((void**)&gz, g_z);
    cudaGetSymbolAddress((void**)&ge, g_e);

    const int smem_node = (2 * 64 * 128 + 3 * 128 + 64) * (int)sizeof(float); // 67328 B
    cudaFuncSetAttribute(node_kernel, cudaFuncAttributeMaxDynamicSharedMemorySize, smem_node);

    const int nodeBlocks = (NN * 32 + 255) / 256;   // 12500
    const int edgeBlocks = (EE * 32 + 255) / 256;   // 200000
    const int zeroBlocks = ((NN * 32) + 255) / 256; // 12500 float4 stores of S

    // encoders
    enc_kernel<<<(NN + 255) / 256, 256>>>(x, enw, enb, gh, NN);
    enc_kernel<<<(EE + 255) / 256, 256>>>(ea, eew, eeb, ge, EE);

    for (int i = 0; i < 4; i++) {
        const float* cin;
        if (i == 0) {
            cin = gh;
        } else {
            lnrelu_kernel<<<nodeBlocks, 256>>>(gh, lng + i * 64, lnb + i * 64, gz);
            cin = gz;
        }
        zero_kernel<<<zeroBlocks, 256>>>();
        edge_kernel<<<edgeBlocks, 256>>>(cin, ei, t + i);
        node_kernel<<<nodeBlocks, 256, smem_node>>>(
            cin, gh, gh,
            w1 + (size_t)i * 64 * 128, b1 + i * 128,
            mg + i * 128, mb + i * 128,
            w2 + (size_t)i * 128 * 64, b2 + i * 64,
            i > 0 ? 1 : 0);
    }

    // final: relu(LN(h, ln_g[0], ln_b[0])) -> d_out
    lnrelu_kernel<<<nodeBlocks, 256>>>(gh, lng, lnb, out);
}

// round 3
// speedup vs baseline: 1.3286x; 1.3286x over previous
#include <cuda_runtime.h>
#include <cuda_fp16.h>

#define NN 100000
#define EE 1600000
#define HD 64

typedef unsigned long long ull;

// ---------------- scratch (device globals; allocation-free rule) ----------------
__device__ __half g_e[(size_t)EE * HD];       // encoded edge features, fp16 (205 MB)
__device__ float  g_h[(size_t)NN * HD];       // node state
__device__ float  g_z[(size_t)NN * HD];       // pre-norm conv input
__device__ float  g_S[(size_t)NN * 2 * HD];   // per-node {ex, msg*ex} per channel

// ---------------- packed f32x2 helpers ----------------
__device__ __forceinline__ ull pk2(float x, float y) {
    ull r; asm("mov.b64 %0, {%1, %2};" : "=l"(r) : "f"(x), "f"(y)); return r;
}
__device__ __forceinline__ float2 upk2(ull v) {
    float2 r; asm("mov.b64 {%0, %1}, %2;" : "=f"(r.x), "=f"(r.y) : "l"(v)); return r;
}
__device__ __forceinline__ ull fma2(ull a, ull b, ull c) {
    ull d; asm("fma.rn.f32x2 %0, %1, %2, %3;" : "=l"(d) : "l"(a), "l"(b), "l"(c)); return d;
}

// ---------------- encoder: Y[M,64] = X[M,64] @ W[64,64] + b ----------------
// acc[j] (ull) holds output channels {2j, 2j+1}
__device__ __forceinline__ void store_row_f32(float* Y, size_t row, const ull* acc) {
    float4* yp = reinterpret_cast<float4*>(Y + row * 64);
#pragma unroll
    for (int m = 0; m < 16; m++) {
        float2 a = upk2(acc[2 * m]), b = upk2(acc[2 * m + 1]);
        yp[m] = make_float4(a.x, a.y, b.x, b.y);
    }
}
__device__ __forceinline__ void store_row_f16(__half* Y, size_t row, const ull* acc) {
    uint4* yp = reinterpret_cast<uint4*>(Y + row * 64);
#pragma unroll
    for (int g = 0; g < 8; g++) {
        uint4 u;
        __half2 h0 = __float22half2_rn(upk2(acc[4 * g + 0]));
        __half2 h1 = __float22half2_rn(upk2(acc[4 * g + 1]));
        __half2 h2 = __float22half2_rn(upk2(acc[4 * g + 2]));
        __half2 h3 = __float22half2_rn(upk2(acc[4 * g + 3]));
        u.x = *reinterpret_cast<unsigned int*>(&h0);
        u.y = *reinterpret_cast<unsigned int*>(&h1);
        u.z = *reinterpret_cast<unsigned int*>(&h2);
        u.w = *reinterpret_cast<unsigned int*>(&h3);
        yp[g] = u;
    }
}

template <typename OUT>
__global__ void enc_kernel(const float* __restrict__ X, const float* __restrict__ W,
                           const float* __restrict__ b, OUT* __restrict__ Y, int M)
{
    __shared__ float Ws[64 * 64];
    __shared__ float bs[64];
    for (int i = threadIdx.x; i < 64 * 64; i += blockDim.x) Ws[i] = W[i];
    if (threadIdx.x < 64) bs[threadIdx.x] = b[threadIdx.x];
    __syncthreads();

    int row = blockIdx.x * blockDim.x + threadIdx.x;
    if (row >= M) return;

    float xr[64];
    const float4* xp = reinterpret_cast<const float4*>(X + (size_t)row * 64);
#pragma unroll
    for (int i = 0; i < 16; i++) {
        float4 v = xp[i];
        xr[4 * i + 0] = v.x; xr[4 * i + 1] = v.y;
        xr[4 * i + 2] = v.z; xr[4 * i + 3] = v.w;
    }

    ull acc[32];
#pragma unroll
    for (int j = 0; j < 32; j++) acc[j] = pk2(bs[2 * j], bs[2 * j + 1]);

#pragma unroll 4
    for (int k = 0; k < 64; k++) {
        ull xk = pk2(xr[k], xr[k]);
        const ulonglong2* wr = reinterpret_cast<const ulonglong2*>(Ws + k * 64);
#pragma unroll
        for (int m = 0; m < 16; m++) {
            ulonglong2 w = wr[m];
            acc[2 * m + 0] = fma2(xk, w.x, acc[2 * m + 0]);
            acc[2 * m + 1] = fma2(xk, w.y, acc[2 * m + 1]);
        }
    }

    if constexpr (sizeof(OUT) == 4) store_row_f32((float*)Y, (size_t)row, acc);
    else                            store_row_f16((__half*)Y, (size_t)row, acc);
}

// ---------------- zero the softmax accumulators (layer 0 only) ----------------
__global__ void zero_kernel()
{
    size_t i = (size_t)blockIdx.x * blockDim.x + threadIdx.x;
    float4* p = reinterpret_cast<float4*>(g_S);
    if (i < (size_t)NN * 32) p[i] = make_float4(0.f, 0.f, 0.f, 0.f);
}

// ---------------- LayerNorm(64) + ReLU (+ optional S zeroing) ----------------
__global__ void lnrelu_kernel(const float* __restrict__ hin, const float* __restrict__ g,
                              const float* __restrict__ b, float* __restrict__ out,
                              int zeroS)
{
    int gt = blockIdx.x * blockDim.x + threadIdx.x;
    int node = gt >> 5;
    if (node >= NN) return;
    int lane = threadIdx.x & 31;

    float2 v = reinterpret_cast<const float2*>(hin + (size_t)node * 64)[lane];
    float s = v.x + v.y;
#pragma unroll
    for (int o = 16; o; o >>= 1) s += __shfl_xor_sync(0xffffffffu, s, o);
    float mu = s * (1.f / 64.f);
    float dx = v.x - mu, dy = v.y - mu;
    float q = dx * dx + dy * dy;
#pragma unroll
    for (int o = 16; o; o >>= 1) q += __shfl_xor_sync(0xffffffffu, q, o);
    float rstd = rsqrtf(q * (1.f / 64.f) + 1e-5f);

    float2 gg = reinterpret_cast<const float2*>(g)[lane];
    float2 bb = reinterpret_cast<const float2*>(b)[lane];
    float2 r;
    r.x = fmaxf(dx * rstd * gg.x + bb.x, 0.f);
    r.y = fmaxf(dy * rstd * gg.y + bb.y, 0.f);
    reinterpret_cast<float2*>(out + (size_t)node * 64)[lane] = r;

    if (zeroS) {
        float4* sp = reinterpret_cast<float4*>(g_S + (size_t)node * 128);
        sp[lane] = make_float4(0.f, 0.f, 0.f, 0.f);
    }
}

// ---------------- edge pass: one warp per edge ----------------
__global__ void edge_kernel(const float* __restrict__ zin, const int* __restrict__ ei,
                            const float* __restrict__ tp)
{
    int gt = blockIdx.x * blockDim.x + threadIdx.x;
    int w = gt >> 5;
    if (w >= EE) return;
    int lane = threadIdx.x & 31;

    int src = __ldg(ei + w);
    int dst = __ldg(ei + EE + w);
    float t = __ldg(tp);

    __half2 eh = reinterpret_cast<const __half2*>(g_e)[(size_t)w * 32 + lane];
    float2 ev = __half22float2(eh);
    float2 hv = reinterpret_cast<const float2*>(zin + (size_t)src * 64)[lane];

    float m0 = fmaxf(hv.x + ev.x, 0.f) + 1e-7f;
    float m1 = fmaxf(hv.y + ev.y, 0.f) + 1e-7f;
    float e0 = __expf(m0 * t);
    float e1 = __expf(m1 * t);

    float* p = g_S + (size_t)dst * 128 + lane * 4;
    asm volatile("red.global.add.v4.f32 [%0], {%1, %2, %3, %4};"
                 :: "l"(p), "f"(e0), "f"(m0 * e0), "f"(e1), "f"(m1 * e1)
                 : "memory");
}

// ---------------- fused node pass: 4 nodes per warp ----------------
__global__ void node_kernel(const float* __restrict__ conv_in,
                            const float* __restrict__ h_in,
                            float* __restrict__ h_out,
                            const float* __restrict__ w1,   // [64][128]
                            const float* __restrict__ b1,   // [128]
                            const float* __restrict__ g1,   // [128]
                            const float* __restrict__ bb1,  // [128]
                            const float* __restrict__ w2,   // [128][64]
                            const float* __restrict__ b2,   // [64]
                            int add_residual)
{
    extern __shared__ float sm[];
    float* w1s  = sm;                 // 8192 floats
    float* w2t  = sm + 8192;          // 8192 floats (transposed: [l][lane][8])
    float* b1s  = sm + 16384;         // 128
    float* g1s  = b1s + 128;          // 128
    float* bb1s = g1s + 128;          // 128
    float* b2s  = bb1s + 128;         // 64

    int tid = threadIdx.x;
    for (int i = tid; i < 64 * 128; i += blockDim.x) w1s[i] = w1[i];
    // w2t[((l*32)+lane)*8 + q*2 + c] = w2[(4l+q)*64 + 2*lane + c]
    for (int i = tid; i < 128 * 64; i += blockDim.x) {
        int l = i >> 8, lane = (i >> 3) & 31, q = (i >> 1) & 3, c = i & 1;
        w2t[i] = w2[(4 * l + q) * 64 + 2 * lane + c];
    }
    if (tid < 128) { b1s[tid] = b1[tid]; g1s[tid] = g1[tid]; bb1s[tid] = bb1[tid]; }
    if (tid < 64)  b2s[tid] = b2[tid];
    __syncthreads();

    int lane = tid & 31;
    int warp = (blockIdx.x * blockDim.x + tid) >> 5;
    int nbase = warp * 4;
    if (nbase >= NN) return;

    // ---- aggregation + root skip ----
    float2 o[4];
#pragma unroll
    for (int n = 0; n < 4; n++) {
        o[n] = make_float2(0.f, 0.f);
        int node = nbase + n;
        if (node < NN) {
            float4 s  = *reinterpret_cast<const float4*>(g_S + (size_t)node * 128 + lane * 4);
            float2 ci = *reinterpret_cast<const float2*>(conv_in + (size_t)node * 64 + lane * 2);
            o[n].x = ci.x + s.y / (s.x + 1e-16f);
            o[n].y = ci.y + s.w / (s.z + 1e-16f);
        }
    }

    // ---- matvec1: z[n] covers output channels 4*lane .. 4*lane+3 ----
    ull z[4][2];
    {
        const ull* bp = reinterpret_cast<const ull*>(b1s);
        ull bi0 = bp[2 * lane], bi1 = bp[2 * lane + 1];
#pragma unroll
        for (int n = 0; n < 4; n++) { z[n][0] = bi0; z[n][1] = bi1; }
    }
#pragma unroll 8
    for (int l = 0; l < 32; l++) {
        ulonglong2 wa = reinterpret_cast<const ulonglong2*>(w1s + (2 * l) * 128)[lane];
        ulonglong2 wb = reinterpret_cast<const ulonglong2*>(w1s + (2 * l + 1) * 128)[lane];
#pragma unroll
        for (int n = 0; n < 4; n++) {
            float a0 = __shfl_sync(0xffffffffu, o[n].x, l);
            float a1 = __shfl_sync(0xffffffffu, o[n].y, l);
            ull a0p = pk2(a0, a0), a1p = pk2(a1, a1);
            z[n][0] = fma2(a0p, wa.x, z[n][0]);
            z[n][1] = fma2(a0p, wa.y, z[n][1]);
            z[n][0] = fma2(a1p, wb.x, z[n][0]);
            z[n][1] = fma2(a1p, wb.y, z[n][1]);
        }
    }

    // ---- LayerNorm(128) + ReLU per node ----
    float4 zf[4];
    float4 gv = *reinterpret_cast<const float4*>(g1s + 4 * lane);
    float4 bv = *reinterpret_cast<const float4*>(bb1s + 4 * lane);
#pragma unroll
    for (int n = 0; n < 4; n++) {
        float2 lo = upk2(z[n][0]), hi = upk2(z[n][1]);
        float ssum = lo.x + lo.y + hi.x + hi.y;
#pragma unroll
        for (int off = 16; off; off >>= 1) ssum += __shfl_xor_sync(0xffffffffu, ssum, off);
        float mu = ssum * (1.f / 128.f);
        float dx = lo.x - mu, dy = lo.y - mu, dz = hi.x - mu, dw = hi.y - mu;
        float sq = dx * dx + dy * dy + dz * dz + dw * dw;
#pragma unroll
        for (int off = 16; off; off >>= 1) sq += __shfl_xor_sync(0xffffffffu, sq, off);
        float rstd = rsqrtf(sq * (1.f / 128.f) + 1e-5f);
        zf[n].x = fmaxf(dx * rstd * gv.x + bv.x, 0.f);
        zf[n].y = fmaxf(dy * rstd * gv.y + bv.y, 0.f);
        zf[n].z = fmaxf(dz * rstd * gv.z + bv.z, 0.f);
        zf[n].w = fmaxf(dw * rstd * gv.w + bv.w, 0.f);
    }

    // ---- matvec2: y[n] covers output channels 2*lane, 2*lane+1 ----
    ull y[4];
    {
        ull bi = reinterpret_cast<const ull*>(b2s)[lane];
#pragma unroll
        for (int n = 0; n < 4; n++) y[n] = bi;
    }
#pragma unroll 8
    for (int l = 0; l < 32; l++) {
        const ulonglong2* wp = reinterpret_cast<const ulonglong2*>(w2t + (l * 32 + lane) * 8);
        ulonglong2 w01 = wp[0];   // k=4l+0 pair, k=4l+1 pair
        ulonglong2 w23 = wp[1];   // k=4l+2 pair, k=4l+3 pair
#pragma unroll
        for (int n = 0; n < 4; n++) {
            float v0 = __shfl_sync(0xffffffffu, zf[n].x, l);
            float v1 = __shfl_sync(0xffffffffu, zf[n].y, l);
            float v2 = __shfl_sync(0xffffffffu, zf[n].z, l);
            float v3 = __shfl_sync(0xffffffffu, zf[n].w, l);
            y[n] = fma2(pk2(v0, v0), w01.x, y[n]);
            y[n] = fma2(pk2(v1, v1), w01.y, y[n]);
            y[n] = fma2(pk2(v2, v2), w23.x, y[n]);
            y[n] = fma2(pk2(v3, v3), w23.y, y[n]);
        }
    }

    // ---- residual + store ----
#pragma unroll
    for (int n = 0; n < 4; n++) {
        int node = nbase + n;
        if (node >= NN) break;
        float2 r = upk2(y[n]);
        if (add_residual) {
            float2 hv = *reinterpret_cast<const float2*>(h_in + (size_t)node * 64 + 2 * lane);
            r.x += hv.x; r.y += hv.y;
        }
        *reinterpret_cast<float2*>(h_out + (size_t)node * 64 + 2 * lane) = r;
    }
}

// ---------------- launch ----------------
extern "C" void kernel_launch(void* const* d_in, const int* in_sizes, int n_in,
                              void* d_out, int out_size)
{
    const float* x   = (const float*)d_in[0];
    const int*   ei  = (const int*)  d_in[1];
    const float* ea  = (const float*)d_in[2];
    const float* enw = (const float*)d_in[3];
    const float* enb = (const float*)d_in[4];
    const float* eew = (const float*)d_in[5];
    const float* eeb = (const float*)d_in[6];
    const float* lng = (const float*)d_in[7];
    const float* lnb = (const float*)d_in[8];
    const float* w1  = (const float*)d_in[9];
    const float* b1  = (const float*)d_in[10];
    const float* mg  = (const float*)d_in[11];
    const float* mb  = (const float*)d_in[12];
    const float* w2  = (const float*)d_in[13];
    const float* b2  = (const float*)d_in[14];
    const float* t   = (const float*)d_in[15];
    float* out = (float*)d_out;

    float *gh, *gz;
    __half* ge;
    cudaGetSymbolAddress((void**)&gh, g_h);
    cudaGetSymbolAddress((void**)&gz, g_z);
    cudaGetSymbolAddress((void**)&ge, g_e);

    const int smem_node = (2 * 64 * 128 + 3 * 128 + 64) * (int)sizeof(float); // 67328 B
    cudaFuncSetAttribute(node_kernel, cudaFuncAttributeMaxDynamicSharedMemorySize, smem_node);

    const int lnBlocks   = (NN * 32 + 255) / 256;           // LN: 1 warp/node
    const int nodeBlocks = ((NN + 3) / 4 * 32 + 255) / 256; // node: 4 nodes/warp
    const int edgeBlocks = (EE * 32 + 255) / 256;
    const int zeroBlocks = ((NN * 32) + 255) / 256;

    // encoders
    enc_kernel<float><<<(NN + 255) / 256, 256>>>(x, enw, enb, gh, NN);
    enc_kernel<__half><<<(EE + 255) / 256, 256>>>(ea, eew, eeb, ge, EE);

    for (int i = 0; i < 4; i++) {
        const float* cin;
        if (i == 0) {
            zero_kernel<<<zeroBlocks, 256>>>();
            cin = gh;
        } else {
            lnrelu_kernel<<<lnBlocks, 256>>>(gh, lng + i * 64, lnb + i * 64, gz, 1);
            cin = gz;
        }
        edge_kernel<<<edgeBlocks, 256>>>(cin, ei, t + i);
        node_kernel<<<nodeBlocks, 256, smem_node>>>(
            cin, gh, gh,
            w1 + (size_t)i * 64 * 128, b1 + i * 128,
            mg + i * 128, mb + i * 128,
            w2 + (size_t)i * 128 * 64, b2 + i * 64,
            i > 0 ? 1 : 0);
    }

    // final: relu(LN(h, ln_g[0], ln_b[0])) -> d_out
    lnrelu_kernel<<<lnBlocks, 256>>>(gh, lng, lnb, out, 0);
}

// round 4
// speedup vs baseline: 1.7972x; 1.3527x over previous
#include <cuda_runtime.h>
#include <cuda_fp16.h>

#define NN 100000
#define EE 1600000
#define NB 98   // ceil(NN/1024)

typedef unsigned long long ull;

// ---------------- scratch (device globals; allocation-free rule) ----------------
__device__ __half g_e[(size_t)EE * 64];      // encoded edge features, fp16, CSR order
__device__ float  g_h[(size_t)NN * 64];      // node state
__device__ float  g_z[(size_t)NN * 64];      // pre-norm conv input (fp32)
__device__ __half g_zh[(size_t)NN * 64];     // gather table (fp16, L2-resident)
__device__ __half g_h16[(size_t)NN * 64];    // fp16 copy of h for layer-0 gather
__device__ float  g_o[(size_t)NN * 64];      // agg output (= conv_in + softmax agg)
__device__ int    g_deg[NN];
__device__ int    g_off[NN + 1];
__device__ int    g_cur[NN];
__device__ int    g_src[EE];                 // src node per CSR slot
__device__ int    g_perm[EE];                // edge -> CSR slot
__device__ int    g_part[128];

// ---------------- packed f32x2 helpers ----------------
__device__ __forceinline__ ull pk2(float x, float y) {
    ull r; asm("mov.b64 %0, {%1, %2};" : "=l"(r) : "f"(x), "f"(y)); return r;
}
__device__ __forceinline__ float2 upk2(ull v) {
    float2 r; asm("mov.b64 {%0, %1}, %2;" : "=f"(r.x), "=f"(r.y) : "l"(v)); return r;
}
__device__ __forceinline__ ull fma2(ull a, ull b, ull c) {
    ull d; asm("fma.rn.f32x2 %0, %1, %2, %3;" : "=l"(d) : "l"(a), "l"(b), "l"(c)); return d;
}

// ================= CSR build =================
__global__ void zerodeg_kernel() {
    int i = blockIdx.x * 1024 + threadIdx.x;
    if (i < NN) g_deg[i] = 0;
}
__global__ void hist_kernel(const int* __restrict__ ei) {
    int e = blockIdx.x * blockDim.x + threadIdx.x;
    if (e >= EE) return;
    atomicAdd(&g_deg[__ldg(ei + EE + e)], 1);
}
__global__ void scan1_kernel() {
    int i = blockIdx.x * 1024 + threadIdx.x;
    int v = (i < NN) ? g_deg[i] : 0;
#pragma unroll
    for (int o = 16; o; o >>= 1) v += __shfl_xor_sync(0xffffffffu, v, o);
    __shared__ int ws[32];
    int lane = threadIdx.x & 31, wid = threadIdx.x >> 5;
    if (lane == 0) ws[wid] = v;
    __syncthreads();
    if (wid == 0) {
        int s = ws[lane];
#pragma unroll
        for (int o = 16; o; o >>= 1) s += __shfl_xor_sync(0xffffffffu, s, o);
        if (lane == 0) g_part[blockIdx.x] = s;
    }
}
__global__ void scan2_kernel() {
    __shared__ int sp[128];
    int tid = threadIdx.x;
    sp[tid] = (tid < NB) ? g_part[tid] : 0;
    __syncthreads();
    if (tid == 0) {
        int acc = 0;
        for (int i = 0; i < NB; i++) { int v = sp[i]; sp[i] = acc; acc += v; }
        g_off[NN] = acc;
    }
    __syncthreads();
    if (tid < NB) g_part[tid] = sp[tid];
}
__global__ void scan3_kernel() {
    int i = blockIdx.x * 1024 + threadIdx.x;
    int lane = threadIdx.x & 31, wid = threadIdx.x >> 5;
    int v = (i < NN) ? g_deg[i] : 0;
    int x = v;
#pragma unroll
    for (int o = 1; o < 32; o <<= 1) {
        int y = __shfl_up_sync(0xffffffffu, x, o);
        if (lane >= o) x += y;
    }
    __shared__ int ws[32];
    if (lane == 31) ws[wid] = x;
    __syncthreads();
    if (wid == 0) {
        int y = ws[lane];
        int z = y;
#pragma unroll
        for (int o = 1; o < 32; o <<= 1) {
            int u = __shfl_up_sync(0xffffffffu, z, o);
            if (lane >= o) z += u;
        }
        ws[lane] = z - y;   // exclusive warp base
    }
    __syncthreads();
    int excl = x - v + ws[wid] + g_part[blockIdx.x];
    if (i < NN) { g_off[i] = excl; g_cur[i] = excl; }
}
__global__ void scatter_kernel(const int* __restrict__ ei) {
    int e = blockIdx.x * blockDim.x + threadIdx.x;
    if (e >= EE) return;
    int dst = __ldg(ei + EE + e);
    int slot = atomicAdd(&g_cur[dst], 1);
    g_src[slot] = __ldg(ei + e);
    g_perm[e] = slot;
}

// ================= encoder: Y[M,64] = X[M,64] @ W[64,64] + b =================
__device__ __forceinline__ void store_row_f32(float* Y, size_t row, const ull* acc) {
    float4* yp = reinterpret_cast<float4*>(Y + row * 64);
#pragma unroll
    for (int m = 0; m < 16; m++) {
        float2 a = upk2(acc[2 * m]), b = upk2(acc[2 * m + 1]);
        yp[m] = make_float4(a.x, a.y, b.x, b.y);
    }
}
__device__ __forceinline__ void store_row_f16(__half* Y, size_t row, const ull* acc) {
    uint4* yp = reinterpret_cast<uint4*>(Y + row * 64);
#pragma unroll
    for (int g = 0; g < 8; g++) {
        uint4 u;
        __half2 h0 = __float22half2_rn(upk2(acc[4 * g + 0]));
        __half2 h1 = __float22half2_rn(upk2(acc[4 * g + 1]));
        __half2 h2 = __float22half2_rn(upk2(acc[4 * g + 2]));
        __half2 h3 = __float22half2_rn(upk2(acc[4 * g + 3]));
        u.x = *reinterpret_cast<unsigned int*>(&h0);
        u.y = *reinterpret_cast<unsigned int*>(&h1);
        u.z = *reinterpret_cast<unsigned int*>(&h2);
        u.w = *reinterpret_cast<unsigned int*>(&h3);
        yp[g] = u;
    }
}

__global__ void enc_kernel(const float* __restrict__ X, const float* __restrict__ W,
                           const float* __restrict__ b,
                           float* Yf, __half* Yh, const int* __restrict__ perm, int M)
{
    __shared__ float Ws[64 * 64];
    __shared__ float bs[64];
    for (int i = threadIdx.x; i < 64 * 64; i += blockDim.x) Ws[i] = W[i];
    if (threadIdx.x < 64) bs[threadIdx.x] = b[threadIdx.x];
    __syncthreads();

    int row = blockIdx.x * blockDim.x + threadIdx.x;
    if (row >= M) return;

    float xr[64];
    const float4* xp = reinterpret_cast<const float4*>(X + (size_t)row * 64);
#pragma unroll
    for (int i = 0; i < 16; i++) {
        float4 v = xp[i];
        xr[4 * i + 0] = v.x; xr[4 * i + 1] = v.y;
        xr[4 * i + 2] = v.z; xr[4 * i + 3] = v.w;
    }

    ull acc[32];
#pragma unroll
    for (int j = 0; j < 32; j++) acc[j] = pk2(bs[2 * j], bs[2 * j + 1]);

#pragma unroll 4
    for (int k = 0; k < 64; k++) {
        ull xk = pk2(xr[k], xr[k]);
        const ulonglong2* wr = reinterpret_cast<const ulonglong2*>(Ws + k * 64);
#pragma unroll
        for (int m = 0; m < 16; m++) {
            ulonglong2 w = wr[m];
            acc[2 * m + 0] = fma2(xk, w.x, acc[2 * m + 0]);
            acc[2 * m + 1] = fma2(xk, w.y, acc[2 * m + 1]);
        }
    }

    if (Yf) store_row_f32(Yf, (size_t)row, acc);
    if (Yh) {
        size_t prow = perm ? (size_t)__ldg(perm + row) : (size_t)row;
        store_row_f16(Yh, prow, acc);
    }
}

// ================= LayerNorm(64) + ReLU (fp32 out + optional fp16 out) =================
__global__ void lnrelu_kernel(const float* __restrict__ hin, const float* __restrict__ g,
                              const float* __restrict__ b, float* __restrict__ out,
                              __half* __restrict__ out16)
{
    int gt = blockIdx.x * blockDim.x + threadIdx.x;
    int node = gt >> 5;
    if (node >= NN) return;
    int lane = threadIdx.x & 31;

    float2 v = reinterpret_cast<const float2*>(hin + (size_t)node * 64)[lane];
    float s = v.x + v.y;
#pragma unroll
    for (int o = 16; o; o >>= 1) s += __shfl_xor_sync(0xffffffffu, s, o);
    float mu = s * (1.f / 64.f);
    float dx = v.x - mu, dy = v.y - mu;
    float q = dx * dx + dy * dy;
#pragma unroll
    for (int o = 16; o; o >>= 1) q += __shfl_xor_sync(0xffffffffu, q, o);
    float rstd = rsqrtf(q * (1.f / 64.f) + 1e-5f);

    float2 gg = reinterpret_cast<const float2*>(g)[lane];
    float2 bb = reinterpret_cast<const float2*>(b)[lane];
    float2 r;
    r.x = fmaxf(dx * rstd * gg.x + bb.x, 0.f);
    r.y = fmaxf(dy * rstd * gg.y + bb.y, 0.f);
    reinterpret_cast<float2*>(out + (size_t)node * 64)[lane] = r;
    if (out16)
        reinterpret_cast<__half2*>(out16)[(size_t)node * 32 + lane] = __float22half2_rn(r);
}

// ================= aggregation: one warp per dst node, CSR gather =================
__global__ void agg_kernel(const float* __restrict__ cin, const __half* __restrict__ ztab,
                           const float* __restrict__ tp, float* __restrict__ outp)
{
    int gt = blockIdx.x * blockDim.x + threadIdx.x;
    int node = gt >> 5;
    if (node >= NN) return;
    int lane = threadIdx.x & 31;
    float t = __ldg(tp);

    int beg = __ldg(g_off + node);
    int end = __ldg(g_off + node + 1);

    const __half2* eb = reinterpret_cast<const __half2*>(g_e);
    const __half2* zb = reinterpret_cast<const __half2*>(ztab);

    float sex0 = 0.f, sex1 = 0.f, smx0 = 0.f, smx1 = 0.f;

#define ACC(EH, ZH) {                                                   \
        float2 ef = __half22float2(EH), zf = __half22float2(ZH);        \
        float m0 = fmaxf(ef.x + zf.x, 0.f) + 1e-7f;                     \
        float m1 = fmaxf(ef.y + zf.y, 0.f) + 1e-7f;                     \
        float p0 = __expf(m0 * t), p1 = __expf(m1 * t);                 \
        sex0 += p0; smx0 += m0 * p0;                                    \
        sex1 += p1; smx1 += m1 * p1; }

    int j = beg;
    for (; j + 4 <= end; j += 4) {
        int s0 = __ldg(g_src + j + 0);
        int s1 = __ldg(g_src + j + 1);
        int s2 = __ldg(g_src + j + 2);
        int s3 = __ldg(g_src + j + 3);
        __half2 e0 = __ldg(eb + (size_t)(j + 0) * 32 + lane);
        __half2 e1 = __ldg(eb + (size_t)(j + 1) * 32 + lane);
        __half2 e2 = __ldg(eb + (size_t)(j + 2) * 32 + lane);
        __half2 e3 = __ldg(eb + (size_t)(j + 3) * 32 + lane);
        __half2 z0 = __ldg(zb + (size_t)s0 * 32 + lane);
        __half2 z1 = __ldg(zb + (size_t)s1 * 32 + lane);
        __half2 z2 = __ldg(zb + (size_t)s2 * 32 + lane);
        __half2 z3 = __ldg(zb + (size_t)s3 * 32 + lane);
        ACC(e0, z0); ACC(e1, z1); ACC(e2, z2); ACC(e3, z3);
    }
    for (; j < end; j++) {
        int s0 = __ldg(g_src + j);
        __half2 e0 = __ldg(eb + (size_t)j * 32 + lane);
        __half2 z0 = __ldg(zb + (size_t)s0 * 32 + lane);
        ACC(e0, z0);
    }
#undef ACC

    float2 ci = reinterpret_cast<const float2*>(cin + (size_t)node * 64)[lane];
    float2 o;
    o.x = ci.x + smx0 / (sex0 + 1e-16f);
    o.y = ci.y + smx1 / (sex1 + 1e-16f);
    reinterpret_cast<float2*>(outp + (size_t)node * 64)[lane] = o;
}

// ================= fused node MLP: 4 nodes per warp =================
__global__ void node_kernel(const float* __restrict__ o_in,
                            const float* __restrict__ h_in,
                            float* __restrict__ h_out,
                            const float* __restrict__ w1,   // [64][128]
                            const float* __restrict__ b1,
                            const float* __restrict__ g1,
                            const float* __restrict__ bb1,
                            const float* __restrict__ w2,   // [128][64]
                            const float* __restrict__ b2,
                            int add_residual)
{
    extern __shared__ float sm[];
    float* w1s  = sm;
    float* w2t  = sm + 8192;
    float* b1s  = sm + 16384;
    float* g1s  = b1s + 128;
    float* bb1s = g1s + 128;
    float* b2s  = bb1s + 128;

    int tid = threadIdx.x;
    for (int i = tid; i < 64 * 128; i += blockDim.x) w1s[i] = w1[i];
    for (int i = tid; i < 128 * 64; i += blockDim.x) {
        int l = i >> 8, lane = (i >> 3) & 31, q = (i >> 1) & 3, c = i & 1;
        w2t[i] = w2[(4 * l + q) * 64 + 2 * lane + c];
    }
    if (tid < 128) { b1s[tid] = b1[tid]; g1s[tid] = g1[tid]; bb1s[tid] = bb1[tid]; }
    if (tid < 64)  b2s[tid] = b2[tid];
    __syncthreads();

    int lane = tid & 31;
    int warp = (blockIdx.x * blockDim.x + tid) >> 5;
    int nbase = warp * 4;
    if (nbase >= NN) return;

    float2 o[4];
#pragma unroll
    for (int n = 0; n < 4; n++) {
        o[n] = make_float2(0.f, 0.f);
        int node = nbase + n;
        if (node < NN)
            o[n] = reinterpret_cast<const float2*>(o_in + (size_t)node * 64)[lane];
    }

    ull z[4][2];
    {
        const ull* bp = reinterpret_cast<const ull*>(b1s);
        ull bi0 = bp[2 * lane], bi1 = bp[2 * lane + 1];
#pragma unroll
        for (int n = 0; n < 4; n++) { z[n][0] = bi0; z[n][1] = bi1; }
    }
#pragma unroll 8
    for (int l = 0; l < 32; l++) {
        ulonglong2 wa = reinterpret_cast<const ulonglong2*>(w1s + (2 * l) * 128)[lane];
        ulonglong2 wb = reinterpret_cast<const ulonglong2*>(w1s + (2 * l + 1) * 128)[lane];
#pragma unroll
        for (int n = 0; n < 4; n++) {
            float a0 = __shfl_sync(0xffffffffu, o[n].x, l);
            float a1 = __shfl_sync(0xffffffffu, o[n].y, l);
            ull a0p = pk2(a0, a0), a1p = pk2(a1, a1);
            z[n][0] = fma2(a0p, wa.x, z[n][0]);
            z[n][1] = fma2(a0p, wa.y, z[n][1]);
            z[n][0] = fma2(a1p, wb.x, z[n][0]);
            z[n][1] = fma2(a1p, wb.y, z[n][1]);
        }
    }

    float4 zf[4];
    float4 gv = *reinterpret_cast<const float4*>(g1s + 4 * lane);
    float4 bv = *reinterpret_cast<const float4*>(bb1s + 4 * lane);
#pragma unroll
    for (int n = 0; n < 4; n++) {
        float2 lo = upk2(z[n][0]), hi = upk2(z[n][1]);
        float ssum = lo.x + lo.y + hi.x + hi.y;
#pragma unroll
        for (int off = 16; off; off >>= 1) ssum += __shfl_xor_sync(0xffffffffu, ssum, off);
        float mu = ssum * (1.f / 128.f);
        float dx = lo.x - mu, dy = lo.y - mu, dz = hi.x - mu, dw = hi.y - mu;
        float sq = dx * dx + dy * dy + dz * dz + dw * dw;
#pragma unroll
        for (int off = 16; off; off >>= 1) sq += __shfl_xor_sync(0xffffffffu, sq, off);
        float rstd = rsqrtf(sq * (1.f / 128.f) + 1e-5f);
        zf[n].x = fmaxf(dx * rstd * gv.x + bv.x, 0.f);
        zf[n].y = fmaxf(dy * rstd * gv.y + bv.y, 0.f);
        zf[n].z = fmaxf(dz * rstd * gv.z + bv.z, 0.f);
        zf[n].w = fmaxf(dw * rstd * gv.w + bv.w, 0.f);
    }

    ull y[4];
    {
        ull bi = reinterpret_cast<const ull*>(b2s)[lane];
#pragma unroll
        for (int n = 0; n < 4; n++) y[n] = bi;
    }
#pragma unroll 8
    for (int l = 0; l < 32; l++) {
        const ulonglong2* wp = reinterpret_cast<const ulonglong2*>(w2t + (l * 32 + lane) * 8);
        ulonglong2 w01 = wp[0];
        ulonglong2 w23 = wp[1];
#pragma unroll
        for (int n = 0; n < 4; n++) {
            float v0 = __shfl_sync(0xffffffffu, zf[n].x, l);
            float v1 = __shfl_sync(0xffffffffu, zf[n].y, l);
            float v2 = __shfl_sync(0xffffffffu, zf[n].z, l);
            float v3 = __shfl_sync(0xffffffffu, zf[n].w, l);
            y[n] = fma2(pk2(v0, v0), w01.x, y[n]);
            y[n] = fma2(pk2(v1, v1), w01.y, y[n]);
            y[n] = fma2(pk2(v2, v2), w23.x, y[n]);
            y[n] = fma2(pk2(v3, v3), w23.y, y[n]);
        }
    }

#pragma unroll
    for (int n = 0; n < 4; n++) {
        int node = nbase + n;
        if (node >= NN) break;
        float2 r = upk2(y[n]);
        if (add_residual) {
            float2 hv = *reinterpret_cast<const float2*>(h_in + (size_t)node * 64 + 2 * lane);
            r.x += hv.x; r.y += hv.y;
        }
        *reinterpret_cast<float2*>(h_out + (size_t)node * 64 + 2 * lane) = r;
    }
}

// ================= launch =================
extern "C" void kernel_launch(void* const* d_in, const int* in_sizes, int n_in,
                              void* d_out, int out_size)
{
    const float* x   = (const float*)d_in[0];
    const int*   ei  = (const int*)  d_in[1];
    const float* ea  = (const float*)d_in[2];
    const float* enw = (const float*)d_in[3];
    const float* enb = (const float*)d_in[4];
    const float* eew = (const float*)d_in[5];
    const float* eeb = (const float*)d_in[6];
    const float* lng = (const float*)d_in[7];
    const float* lnb = (const float*)d_in[8];
    const float* w1  = (const float*)d_in[9];
    const float* b1  = (const float*)d_in[10];
    const float* mg  = (const float*)d_in[11];
    const float* mb  = (const float*)d_in[12];
    const float* w2  = (const float*)d_in[13];
    const float* b2  = (const float*)d_in[14];
    const float* t   = (const float*)d_in[15];
    float* out = (float*)d_out;

    float *gh, *gz, *go;
    __half *ge, *gzh, *gh16;
    int* gperm;
    cudaGetSymbolAddress((void**)&gh, g_h);
    cudaGetSymbolAddress((void**)&gz, g_z);
    cudaGetSymbolAddress((void**)&go, g_o);
    cudaGetSymbolAddress((void**)&ge, g_e);
    cudaGetSymbolAddress((void**)&gzh, g_zh);
    cudaGetSymbolAddress((void**)&gh16, g_h16);
    cudaGetSymbolAddress((void**)&gperm, g_perm);

    const int smem_node = (2 * 64 * 128 + 3 * 128 + 64) * (int)sizeof(float); // 67328 B
    cudaFuncSetAttribute(node_kernel, cudaFuncAttributeMaxDynamicSharedMemorySize, smem_node);

    const int warpNodeBlocks = (NN * 32 + 255) / 256;            // 1 warp/node kernels
    const int nodeBlocks     = ((NN + 3) / 4 * 32 + 255) / 256;  // 4 nodes/warp
    const int edgeTB         = (EE + 255) / 256;

    // ---- CSR build ----
    zerodeg_kernel<<<NB, 1024>>>();
    hist_kernel<<<edgeTB, 256>>>(ei);
    scan1_kernel<<<NB, 1024>>>();
    scan2_kernel<<<1, 128>>>();
    scan3_kernel<<<NB, 1024>>>();
    scatter_kernel<<<edgeTB, 256>>>(ei);

    // ---- encoders ----
    enc_kernel<<<(NN + 255) / 256, 256>>>(x, enw, enb, gh, gh16, (const int*)nullptr, NN);
    enc_kernel<<<edgeTB, 256>>>(ea, eew, eeb, (float*)nullptr, ge, gperm, EE);

    // ---- layers ----
    for (int i = 0; i < 4; i++) {
        const float* cin32;
        const __half* ztab;
        if (i == 0) { cin32 = gh; ztab = gh16; }
        else {
            lnrelu_kernel<<<warpNodeBlocks, 256>>>(gh, lng + i * 64, lnb + i * 64, gz, gzh);
            cin32 = gz; ztab = gzh;
        }
        agg_kernel<<<warpNodeBlocks, 256>>>(cin32, ztab, t + i, go);
        node_kernel<<<nodeBlocks, 256, smem_node>>>(
            go, gh, gh,
            w1 + (size_t)i * 64 * 128, b1 + i * 128,
            mg + i * 128, mb + i * 128,
            w2 + (size_t)i * 128 * 64, b2 + i * 64,
            i > 0 ? 1 : 0);
    }

    // ---- final: relu(LN(h, ln_g[0], ln_b[0])) -> d_out ----
    lnrelu_kernel<<<warpNodeBlocks, 256>>>(gh, lng, lnb, out, (__half*)nullptr);
}

// round 5
// speedup vs baseline: 1.8826x; 1.0475x over previous
#include <cuda_runtime.h>
#include <cuda_fp16.h>

#define NN 100000
#define EE 1600000
#define NB 98   // ceil(NN/1024)

typedef unsigned long long ull;

// ---------------- scratch (device globals; allocation-free rule) ----------------
__device__ __half g_e[(size_t)EE * 64];      // encoded edge features, fp16, CSR order
__device__ float  g_h[(size_t)NN * 64];      // node state
__device__ float  g_z[(size_t)NN * 64];      // pre-norm conv input (fp32)
__device__ __half g_zh[(size_t)NN * 64];     // gather table (fp16, L2-resident)
__device__ __half g_h16[(size_t)NN * 64];    // fp16 copy of h for layer-0 gather
__device__ float  g_o[(size_t)NN * 64];      // agg output (= conv_in + softmax agg)
__device__ int    g_deg[NN];
__device__ int    g_off[NN + 1];
__device__ int    g_cur[NN];
__device__ int    g_src[EE];                 // src node per CSR slot
__device__ int    g_perm[EE];                // edge -> CSR slot
__device__ int    g_part[128];

// ---------------- packed f32x2 helpers ----------------
__device__ __forceinline__ ull pk2(float x, float y) {
    ull r; asm("mov.b64 %0, {%1, %2};" : "=l"(r) : "f"(x), "f"(y)); return r;
}
__device__ __forceinline__ float2 upk2(ull v) {
    float2 r; asm("mov.b64 {%0, %1}, %2;" : "=f"(r.x), "=f"(r.y) : "l"(v)); return r;
}
__device__ __forceinline__ ull fma2(ull a, ull b, ull c) {
    ull d; asm("fma.rn.f32x2 %0, %1, %2, %3;" : "=l"(d) : "l"(a), "l"(b), "l"(c)); return d;
}

// ================= CSR build =================
__global__ void zerodeg_kernel() {
    int i = blockIdx.x * 1024 + threadIdx.x;
    if (i < NN) g_deg[i] = 0;
}
__global__ void hist_kernel(const int* __restrict__ ei) {
    int e = blockIdx.x * blockDim.x + threadIdx.x;
    if (e >= EE) return;
    atomicAdd(&g_deg[__ldg(ei + EE + e)], 1);
}
__global__ void scan1_kernel() {
    int i = blockIdx.x * 1024 + threadIdx.x;
    int v = (i < NN) ? g_deg[i] : 0;
#pragma unroll
    for (int o = 16; o; o >>= 1) v += __shfl_xor_sync(0xffffffffu, v, o);
    __shared__ int ws[32];
    int lane = threadIdx.x & 31, wid = threadIdx.x >> 5;
    if (lane == 0) ws[wid] = v;
    __syncthreads();
    if (wid == 0) {
        int s = ws[lane];
#pragma unroll
        for (int o = 16; o; o >>= 1) s += __shfl_xor_sync(0xffffffffu, s, o);
        if (lane == 0) g_part[blockIdx.x] = s;
    }
}
__global__ void scan2_kernel() {
    __shared__ int sp[128];
    int tid = threadIdx.x;
    sp[tid] = (tid < NB) ? g_part[tid] : 0;
    __syncthreads();
    if (tid == 0) {
        int acc = 0;
        for (int i = 0; i < NB; i++) { int v = sp[i]; sp[i] = acc; acc += v; }
        g_off[NN] = acc;
    }
    __syncthreads();
    if (tid < NB) g_part[tid] = sp[tid];
}
__global__ void scan3_kernel() {
    int i = blockIdx.x * 1024 + threadIdx.x;
    int lane = threadIdx.x & 31, wid = threadIdx.x >> 5;
    int v = (i < NN) ? g_deg[i] : 0;
    int x = v;
#pragma unroll
    for (int o = 1; o < 32; o <<= 1) {
        int y = __shfl_up_sync(0xffffffffu, x, o);
        if (lane >= o) x += y;
    }
    __shared__ int ws[32];
    if (lane == 31) ws[wid] = x;
    __syncthreads();
    if (wid == 0) {
        int y = ws[lane];
        int z = y;
#pragma unroll
        for (int o = 1; o < 32; o <<= 1) {
            int u = __shfl_up_sync(0xffffffffu, z, o);
            if (lane >= o) z += u;
        }
        ws[lane] = z - y;   // exclusive warp base
    }
    __syncthreads();
    int excl = x - v + ws[wid] + g_part[blockIdx.x];
    if (i < NN) { g_off[i] = excl; g_cur[i] = excl; }
}
__global__ void scatter_kernel(const int* __restrict__ ei) {
    int e = blockIdx.x * blockDim.x + threadIdx.x;
    if (e >= EE) return;
    int dst = __ldg(ei + EE + e);
    int slot = atomicAdd(&g_cur[dst], 1);
    g_src[slot] = __ldg(ei + e);
    g_perm[e] = slot;
}

// ================= encoder: Y[M,64] = X[M,64] @ W[64,64] + b =================
// 2-pass output accumulation to keep register count ~110 (no spills).
__global__ void enc_kernel(const float* __restrict__ X, const float* __restrict__ W,
                           const float* __restrict__ b,
                           float* Yf, __half* Yh, const int* __restrict__ perm, int M)
{
    __shared__ float Ws[64 * 64];
    __shared__ float bs[64];
    for (int i = threadIdx.x; i < 64 * 64; i += blockDim.x) Ws[i] = W[i];
    if (threadIdx.x < 64) bs[threadIdx.x] = b[threadIdx.x];
    __syncthreads();

    int row = blockIdx.x * blockDim.x + threadIdx.x;
    if (row >= M) return;

    float xr[64];
    const float4* xp = reinterpret_cast<const float4*>(X + (size_t)row * 64);
#pragma unroll
    for (int i = 0; i < 16; i++) {
        float4 v = xp[i];
        xr[4 * i + 0] = v.x; xr[4 * i + 1] = v.y;
        xr[4 * i + 2] = v.z; xr[4 * i + 3] = v.w;
    }

    size_t prow = perm ? (size_t)__ldg(perm + row) : (size_t)row;

#pragma unroll
    for (int half = 0; half < 2; half++) {
        ull acc[16];
#pragma unroll
        for (int j = 0; j < 16; j++)
            acc[j] = pk2(bs[half * 32 + 2 * j], bs[half * 32 + 2 * j + 1]);

#pragma unroll 8
        for (int k = 0; k < 64; k++) {
            ull xk = pk2(xr[k], xr[k]);
            const ulonglong2* wr = reinterpret_cast<const ulonglong2*>(Ws + k * 64 + half * 32);
#pragma unroll
            for (int m = 0; m < 8; m++) {
                ulonglong2 w = wr[m];
                acc[2 * m + 0] = fma2(xk, w.x, acc[2 * m + 0]);
                acc[2 * m + 1] = fma2(xk, w.y, acc[2 * m + 1]);
            }
        }

        if (Yf) {
            float4* yp = reinterpret_cast<float4*>(Yf + (size_t)row * 64 + half * 32);
#pragma unroll
            for (int m = 0; m < 8; m++) {
                float2 a = upk2(acc[2 * m]), c = upk2(acc[2 * m + 1]);
                yp[m] = make_float4(a.x, a.y, c.x, c.y);
            }
        }
        if (Yh) {
            uint4* yp = reinterpret_cast<uint4*>(Yh + prow * 64 + half * 32);
#pragma unroll
            for (int g = 0; g < 4; g++) {
                __half2 h0 = __float22half2_rn(upk2(acc[4 * g + 0]));
                __half2 h1 = __float22half2_rn(upk2(acc[4 * g + 1]));
                __half2 h2 = __float22half2_rn(upk2(acc[4 * g + 2]));
                __half2 h3 = __float22half2_rn(upk2(acc[4 * g + 3]));
                uint4 u;
                u.x = *reinterpret_cast<unsigned int*>(&h0);
                u.y = *reinterpret_cast<unsigned int*>(&h1);
                u.z = *reinterpret_cast<unsigned int*>(&h2);
                u.w = *reinterpret_cast<unsigned int*>(&h3);
                yp[g] = u;
            }
        }
    }
}

// ================= aggregation: one warp per dst node, CSR gather =================
__global__ void agg_kernel(const float* __restrict__ cin, const __half* __restrict__ ztab,
                           const float* __restrict__ tp, float* __restrict__ outp)
{
    int gt = blockIdx.x * blockDim.x + threadIdx.x;
    int node = gt >> 5;
    if (node >= NN) return;
    int lane = threadIdx.x & 31;
    float t = __ldg(tp);

    int beg = __ldg(g_off + node);
    int end = __ldg(g_off + node + 1);

    const __half2* eb = reinterpret_cast<const __half2*>(g_e);
    const __half2* zb = reinterpret_cast<const __half2*>(ztab);

    float sex0 = 0.f, sex1 = 0.f, smx0 = 0.f, smx1 = 0.f;

#define ACC(EH, ZH) {                                                   \
        float2 ef = __half22float2(EH), zf = __half22float2(ZH);        \
        float m0 = fmaxf(ef.x + zf.x, 0.f) + 1e-7f;                     \
        float m1 = fmaxf(ef.y + zf.y, 0.f) + 1e-7f;                     \
        float p0 = __expf(m0 * t), p1 = __expf(m1 * t);                 \
        sex0 += p0; smx0 += m0 * p0;                                    \
        sex1 += p1; smx1 += m1 * p1; }

    int j = beg;
    for (; j + 4 <= end; j += 4) {
        int s0 = __ldcs(g_src + j + 0);
        int s1 = __ldcs(g_src + j + 1);
        int s2 = __ldcs(g_src + j + 2);
        int s3 = __ldcs(g_src + j + 3);
        __half2 e0 = __ldcs(eb + (size_t)(j + 0) * 32 + lane);
        __half2 e1 = __ldcs(eb + (size_t)(j + 1) * 32 + lane);
        __half2 e2 = __ldcs(eb + (size_t)(j + 2) * 32 + lane);
        __half2 e3 = __ldcs(eb + (size_t)(j + 3) * 32 + lane);
        __half2 z0 = __ldg(zb + (size_t)s0 * 32 + lane);
        __half2 z1 = __ldg(zb + (size_t)s1 * 32 + lane);
        __half2 z2 = __ldg(zb + (size_t)s2 * 32 + lane);
        __half2 z3 = __ldg(zb + (size_t)s3 * 32 + lane);
        ACC(e0, z0); ACC(e1, z1); ACC(e2, z2); ACC(e3, z3);
    }
    for (; j < end; j++) {
        int s0 = __ldcs(g_src + j);
        __half2 e0 = __ldcs(eb + (size_t)j * 32 + lane);
        __half2 z0 = __ldg(zb + (size_t)s0 * 32 + lane);
        ACC(e0, z0);
    }
#undef ACC

    float2 ci = reinterpret_cast<const float2*>(cin + (size_t)node * 64)[lane];
    float2 o;
    o.x = ci.x + smx0 / (sex0 + 1e-16f);
    o.y = ci.y + smx1 / (sex1 + 1e-16f);
    reinterpret_cast<float2*>(outp + (size_t)node * 64)[lane] = o;
}

// ================= fused node MLP (persistent, 4 nodes/warp) + next-LN epilogue =================
// h_new = (res? h_in:0) + MLP(o_in); if write_h: h_out = h_new.
// epilogue: r = relu(LN(h_new, nlg, nlb)); z32 = r; if z16: z16 = half(r).
__global__ void node_kernel(const float* __restrict__ o_in,
                            const float* __restrict__ h_in,
                            float* __restrict__ h_out,
                            const float* __restrict__ w1,   // [64][128]
                            const float* __restrict__ b1,
                            const float* __restrict__ g1,
                            const float* __restrict__ bb1,
                            const float* __restrict__ w2,   // [128][64]
                            const float* __restrict__ b2,
                            const float* __restrict__ nlg,  // next LN gamma [64]
                            const float* __restrict__ nlb,  // next LN beta  [64]
                            float* __restrict__ z32,
                            __half* __restrict__ z16,
                            int add_residual, int write_h)
{
    extern __shared__ float sm[];
    float* w1s  = sm;
    float* w2t  = sm + 8192;
    float* b1s  = sm + 16384;
    float* g1s  = b1s + 128;
    float* bb1s = g1s + 128;
    float* b2s  = bb1s + 128;

    int tid = threadIdx.x;
    for (int i = tid; i < 64 * 128; i += blockDim.x) w1s[i] = w1[i];
    for (int i = tid; i < 128 * 64; i += blockDim.x) {
        int l = i >> 8, lane = (i >> 3) & 31, q = (i >> 1) & 3, c = i & 1;
        w2t[i] = w2[(4 * l + q) * 64 + 2 * lane + c];
    }
    if (tid < 128) { b1s[tid] = b1[tid]; g1s[tid] = g1[tid]; bb1s[tid] = bb1[tid]; }
    if (tid < 64)  b2s[tid] = b2[tid];
    __syncthreads();

    int lane = tid & 31;
    // next-LN params cached per lane (channels 2*lane, 2*lane+1)
    float2 ngg = reinterpret_cast<const float2*>(nlg)[lane];
    float2 nbb = reinterpret_cast<const float2*>(nlb)[lane];
    float4 gv = *reinterpret_cast<const float4*>(g1s + 4 * lane);
    float4 bv = *reinterpret_cast<const float4*>(bb1s + 4 * lane);
    ull bi0, bi1, bi2;
    {
        const ull* bp = reinterpret_cast<const ull*>(b1s);
        bi0 = bp[2 * lane]; bi1 = bp[2 * lane + 1];
        bi2 = reinterpret_cast<const ull*>(b2s)[lane];
    }

    int warpId = (blockIdx.x * blockDim.x + tid) >> 5;
    int nWarps = (gridDim.x * blockDim.x) >> 5;
    const int nGroups = NN / 4;  // NN divisible by 4

    for (int grp = warpId; grp < nGroups; grp += nWarps) {
        int nbase = grp * 4;

        float2 o[4];
#pragma unroll
        for (int n = 0; n < 4; n++)
            o[n] = reinterpret_cast<const float2*>(o_in + (size_t)(nbase + n) * 64)[lane];

        // ---- matvec1 ----
        ull z[4][2];
#pragma unroll
        for (int n = 0; n < 4; n++) { z[n][0] = bi0; z[n][1] = bi1; }
#pragma unroll 8
        for (int l = 0; l < 32; l++) {
            ulonglong2 wa = reinterpret_cast<const ulonglong2*>(w1s + (2 * l) * 128)[lane];
            ulonglong2 wb = reinterpret_cast<const ulonglong2*>(w1s + (2 * l + 1) * 128)[lane];
#pragma unroll
            for (int n = 0; n < 4; n++) {
                float a0 = __shfl_sync(0xffffffffu, o[n].x, l);
                float a1 = __shfl_sync(0xffffffffu, o[n].y, l);
                ull a0p = pk2(a0, a0), a1p = pk2(a1, a1);
                z[n][0] = fma2(a0p, wa.x, z[n][0]);
                z[n][1] = fma2(a0p, wa.y, z[n][1]);
                z[n][0] = fma2(a1p, wb.x, z[n][0]);
                z[n][1] = fma2(a1p, wb.y, z[n][1]);
            }
        }

        // ---- LayerNorm(128) + ReLU ----
        float4 zf[4];
#pragma unroll
        for (int n = 0; n < 4; n++) {
            float2 lo = upk2(z[n][0]), hi = upk2(z[n][1]);
            float ssum = lo.x + lo.y + hi.x + hi.y;
#pragma unroll
            for (int off = 16; off; off >>= 1) ssum += __shfl_xor_sync(0xffffffffu, ssum, off);
            float mu = ssum * (1.f / 128.f);
            float dx = lo.x - mu, dy = lo.y - mu, dz = hi.x - mu, dw = hi.y - mu;
            float sq = dx * dx + dy * dy + dz * dz + dw * dw;
#pragma unroll
            for (int off = 16; off; off >>= 1) sq += __shfl_xor_sync(0xffffffffu, sq, off);
            float rstd = rsqrtf(sq * (1.f / 128.f) + 1e-5f);
            zf[n].x = fmaxf(dx * rstd * gv.x + bv.x, 0.f);
            zf[n].y = fmaxf(dy * rstd * gv.y + bv.y, 0.f);
            zf[n].z = fmaxf(dz * rstd * gv.z + bv.z, 0.f);
            zf[n].w = fmaxf(dw * rstd * gv.w + bv.w, 0.f);
        }

        // ---- matvec2 ----
        ull y[4];
#pragma unroll
        for (int n = 0; n < 4; n++) y[n] = bi2;
#pragma unroll 8
        for (int l = 0; l < 32; l++) {
            const ulonglong2* wp = reinterpret_cast<const ulonglong2*>(w2t + (l * 32 + lane) * 8);
            ulonglong2 w01 = wp[0];
            ulonglong2 w23 = wp[1];
#pragma unroll
            for (int n = 0; n < 4; n++) {
                float v0 = __shfl_sync(0xffffffffu, zf[n].x, l);
                float v1 = __shfl_sync(0xffffffffu, zf[n].y, l);
                float v2 = __shfl_sync(0xffffffffu, zf[n].z, l);
                float v3 = __shfl_sync(0xffffffffu, zf[n].w, l);
                y[n] = fma2(pk2(v0, v0), w01.x, y[n]);
                y[n] = fma2(pk2(v1, v1), w01.y, y[n]);
                y[n] = fma2(pk2(v2, v2), w23.x, y[n]);
                y[n] = fma2(pk2(v3, v3), w23.y, y[n]);
            }
        }

        // ---- residual + h store + next-LN epilogue ----
#pragma unroll
        for (int n = 0; n < 4; n++) {
            int node = nbase + n;
            float2 r = upk2(y[n]);
            if (add_residual) {
                float2 hv = *reinterpret_cast<const float2*>(h_in + (size_t)node * 64 + 2 * lane);
                r.x += hv.x; r.y += hv.y;
            }
            if (write_h)
                *reinterpret_cast<float2*>(h_out + (size_t)node * 64 + 2 * lane) = r;

            // LN(64) + ReLU with next-layer params
            float s = r.x + r.y;
#pragma unroll
            for (int off = 16; off; off >>= 1) s += __shfl_xor_sync(0xffffffffu, s, off);
            float mu = s * (1.f / 64.f);
            float dx = r.x - mu, dy = r.y - mu;
            float q = dx * dx + dy * dy;
#pragma unroll
            for (int off = 16; off; off >>= 1) q += __shfl_xor_sync(0xffffffffu, q, off);
            float rstd = rsqrtf(q * (1.f / 64.f) + 1e-5f);
            float2 zr;
            zr.x = fmaxf(dx * rstd * ngg.x + nbb.x, 0.f);
            zr.y = fmaxf(dy * rstd * ngg.y + nbb.y, 0.f);
            reinterpret_cast<float2*>(z32 + (size_t)node * 64 + 2 * lane)[0] = zr;
            if (z16)
                reinterpret_cast<__half2*>(z16)[(size_t)node * 32 + lane] = __float22half2_rn(zr);
        }
    }
}

// ================= launch =================
extern "C" void kernel_launch(void* const* d_in, const int* in_sizes, int n_in,
                              void* d_out, int out_size)
{
    const float* x   = (const float*)d_in[0];
    const int*   ei  = (const int*)  d_in[1];
    const float* ea  = (const float*)d_in[2];
    const float* enw = (const float*)d_in[3];
    const float* enb = (const float*)d_in[4];
    const float* eew = (const float*)d_in[5];
    const float* eeb = (const float*)d_in[6];
    const float* lng = (const float*)d_in[7];
    const float* lnb = (const float*)d_in[8];
    const float* w1  = (const float*)d_in[9];
    const float* b1  = (const float*)d_in[10];
    const float* mg  = (const float*)d_in[11];
    const float* mb  = (const float*)d_in[12];
    const float* w2  = (const float*)d_in[13];
    const float* b2  = (const float*)d_in[14];
    const float* t   = (const float*)d_in[15];
    float* out = (float*)d_out;

    float *gh, *gz, *go;
    __half *ge, *gzh, *gh16;
    int* gperm;
    cudaGetSymbolAddress((void**)&gh, g_h);
    cudaGetSymbolAddress((void**)&gz, g_z);
    cudaGetSymbolAddress((void**)&go, g_o);
    cudaGetSymbolAddress((void**)&ge, g_e);
    cudaGetSymbolAddress((void**)&gzh, g_zh);
    cudaGetSymbolAddress((void**)&gh16, g_h16);
    cudaGetSymbolAddress((void**)&gperm, g_perm);

    const int smem_node = (2 * 64 * 128 + 3 * 128 + 64) * (int)sizeof(float); // 67328 B
    cudaFuncSetAttribute(node_kernel, cudaFuncAttributeMaxDynamicSharedMemorySize, smem_node);

    const int warpNodeBlocks = (NN * 32 + 255) / 256;   // agg: 1 warp/node
    const int edgeTB         = (EE + 255) / 256;
    const int persistBlocks  = 444;                     // 3 CTAs/SM x 148 SMs

    // ---- CSR build ----
    zerodeg_kernel<<<NB, 1024>>>();
    hist_kernel<<<edgeTB, 256>>>(ei);
    scan1_kernel<<<NB, 1024>>>();
    scan2_kernel<<<1, 128>>>();
    scan3_kernel<<<NB, 1024>>>();
    scatter_kernel<<<edgeTB, 256>>>(ei);

    // ---- encoders ----
    enc_kernel<<<(NN + 255) / 256, 256>>>(x, enw, enb, gh, gh16, (const int*)nullptr, NN);
    enc_kernel<<<edgeTB, 256>>>(ea, eew, eeb, (float*)nullptr, ge, gperm, EE);

    // ---- layers (LN fused into node epilogue) ----
    for (int i = 0; i < 4; i++) {
        const float* cin32  = (i == 0) ? gh   : gz;
        const __half* ztab  = (i == 0) ? gh16 : gzh;
        agg_kernel<<<warpNodeBlocks, 256>>>(cin32, ztab, t + i, go);

        int last = (i == 3);
        // epilogue LN params: next layer's pre-norm, or ln[0] for the final output
        const float* nlg = lng + (last ? 0 : (i + 1)) * 64;
        const float* nlb = lnb + (last ? 0 : (i + 1)) * 64;
        node_kernel<<<persistBlocks, 256, smem_node>>>(
            go, gh, gh,
            w1 + (size_t)i * 64 * 128, b1 + i * 128,
            mg + i * 128, mb + i * 128,
            w2 + (size_t)i * 128 * 64, b2 + i * 64,
            nlg, nlb,
            last ? out : gz, last ? (__half*)nullptr : gzh,
            i > 0 ? 1 : 0, last ? 0 : 1);
    }
}

// round 6
// speedup vs baseline: 2.0498x; 1.0888x over previous
#include <cuda_runtime.h>
#include <cuda_fp16.h>

#define NN 100000
#define EE 1600000
#define NB 98   // ceil(NN/1024)

typedef unsigned long long ull;

// ---------------- scratch (device globals; allocation-free rule) ----------------
__device__ __half g_e[(size_t)EE * 64];      // encoded edge features, fp16, CSR order
__device__ float  g_h[(size_t)NN * 64];      // node state
__device__ float  g_z[(size_t)NN * 64];      // pre-norm conv input (fp32)
__device__ __half g_zh[(size_t)NN * 64];     // gather table (fp16, L2-resident)
__device__ __half g_h16[(size_t)NN * 64];    // fp16 copy of h for layer-0 gather
__device__ float  g_o[(size_t)NN * 64];      // agg output
__device__ int    g_deg[NN];
__device__ int    g_off[NN + 1];
__device__ int    g_cur[NN];
__device__ int    g_src[EE];
__device__ int    g_perm[EE];
__device__ int    g_part[128];

// ---------------- packed f32x2 helpers ----------------
__device__ __forceinline__ ull pk2(float x, float y) {
    ull r; asm("mov.b64 %0, {%1, %2};" : "=l"(r) : "f"(x), "f"(y)); return r;
}
__device__ __forceinline__ float2 upk2(ull v) {
    float2 r; asm("mov.b64 {%0, %1}, %2;" : "=f"(r.x), "=f"(r.y) : "l"(v)); return r;
}
__device__ __forceinline__ ull fma2(ull a, ull b, ull c) {
    ull d; asm("fma.rn.f32x2 %0, %1, %2, %3;" : "=l"(d) : "l"(a), "l"(b), "l"(c)); return d;
}

// ================= CSR build =================
__global__ void hist_kernel(const int* __restrict__ ei) {
    int e = blockIdx.x * blockDim.x + threadIdx.x;
    if (e >= EE) return;
    atomicAdd(&g_deg[__ldg(ei + EE + e)], 1);
}
__global__ void scan1_kernel() {
    int i = blockIdx.x * 1024 + threadIdx.x;
    int v = (i < NN) ? g_deg[i] : 0;
#pragma unroll
    for (int o = 16; o; o >>= 1) v += __shfl_xor_sync(0xffffffffu, v, o);
    __shared__ int ws[32];
    int lane = threadIdx.x & 31, wid = threadIdx.x >> 5;
    if (lane == 0) ws[wid] = v;
    __syncthreads();
    if (wid == 0) {
        int s = ws[lane];
#pragma unroll
        for (int o = 16; o; o >>= 1) s += __shfl_xor_sync(0xffffffffu, s, o);
        if (lane == 0) g_part[blockIdx.x] = s;
    }
}
__global__ void scan2_kernel() {
    __shared__ int sp[128];
    int tid = threadIdx.x;
    sp[tid] = (tid < NB) ? g_part[tid] : 0;
    __syncthreads();
    if (tid == 0) {
        int acc = 0;
        for (int i = 0; i < NB; i++) { int v = sp[i]; sp[i] = acc; acc += v; }
        g_off[NN] = acc;
    }
    __syncthreads();
    if (tid < NB) g_part[tid] = sp[tid];
}
__global__ void scan3_kernel() {
    int i = blockIdx.x * 1024 + threadIdx.x;
    int lane = threadIdx.x & 31, wid = threadIdx.x >> 5;
    int v = (i < NN) ? g_deg[i] : 0;
    int x = v;
#pragma unroll
    for (int o = 1; o < 32; o <<= 1) {
        int y = __shfl_up_sync(0xffffffffu, x, o);
        if (lane >= o) x += y;
    }
    __shared__ int ws[32];
    if (lane == 31) ws[wid] = x;
    __syncthreads();
    if (wid == 0) {
        int y = ws[lane];
        int z = y;
#pragma unroll
        for (int o = 1; o < 32; o <<= 1) {
            int u = __shfl_up_sync(0xffffffffu, z, o);
            if (lane >= o) z += u;
        }
        ws[lane] = z - y;
    }
    __syncthreads();
    int excl = x - v + ws[wid] + g_part[blockIdx.x];
    if (i < NN) { g_off[i] = excl; g_cur[i] = excl; }
}
__global__ void scatter_kernel(const int* __restrict__ ei) {
    int e = blockIdx.x * blockDim.x + threadIdx.x;
    if (e >= EE) return;
    int dst = __ldg(ei + EE + e);
    int slot = atomicAdd(&g_cur[dst], 1);
    g_src[slot] = __ldg(ei + e);
    g_perm[e] = slot;
}

// ================= encoder: Y[M,64] = X[M,64] @ W[64,64] + b =================
// Warp-cooperative smem staging for coalesced gmem IO; thread-per-row compute.
// If Yf: write fp32 rows (+optional fp16 copy Yh, same row index).
// If Yf==null: write fp16 rows to Yh at perm-scattered row indices.
__global__ void __launch_bounds__(128) enc_kernel(
    const float* __restrict__ X, const float* __restrict__ W,
    const float* __restrict__ b,
    float* __restrict__ Yf, __half* __restrict__ Yh,
    const int* __restrict__ perm, int M)
{
    extern __shared__ float esm[];
    float* Ws = esm;            // 4096 floats
    float* bs = esm + 4096;     // 64
    ull* stage = (ull*)(esm + 4160);   // 4 warps * 32 rows * 33 ull (264B pitch)

    int tid = threadIdx.x;
    for (int i = tid; i < 4096; i += blockDim.x) Ws[i] = W[i];
    if (tid < 64) bs[tid] = b[tid];
    __syncthreads();

    int lane = tid & 31;
    int w = tid >> 5;
    ull* st = stage + (size_t)w * (33 * 32);
    int base = blockIdx.x * blockDim.x + w * 32;

    int permr = 0;
    if (perm) { int rr = base + lane; permr = (rr < M) ? __ldg(perm + rr) : 0; }

    // coalesced load: 32 rows, 256B each
#pragma unroll 4
    for (int r = 0; r < 32; r++) {
        int row = base + r;
        if (row < M)
            st[r * 33 + lane] = *reinterpret_cast<const ull*>(X + (size_t)row * 64 + 2 * lane);
    }
    __syncwarp();

    // each thread reads its own row from smem (2-way conflicts max)
    float xr[64];
    {
        const ull* rp = st + lane * 33;
#pragma unroll
        for (int g2 = 0; g2 < 32; g2++) {
            float2 v = upk2(rp[g2]);
            xr[2 * g2] = v.x; xr[2 * g2 + 1] = v.y;
        }
    }
    __syncwarp();   // stage will be overwritten with outputs

    // 2-pass matvec (16 ull accs per pass)
#pragma unroll
    for (int half = 0; half < 2; half++) {
        ull acc[16];
#pragma unroll
        for (int j = 0; j < 16; j++)
            acc[j] = pk2(bs[half * 32 + 2 * j], bs[half * 32 + 2 * j + 1]);

#pragma unroll 8
        for (int k = 0; k < 64; k++) {
            ull xk = pk2(xr[k], xr[k]);
            const ulonglong2* wr = reinterpret_cast<const ulonglong2*>(Ws + k * 64 + half * 32);
#pragma unroll
            for (int m = 0; m < 8; m++) {
                ulonglong2 ww = wr[m];
                acc[2 * m + 0] = fma2(xk, ww.x, acc[2 * m + 0]);
                acc[2 * m + 1] = fma2(xk, ww.y, acc[2 * m + 1]);
            }
        }

        ull* op = st + lane * 33;
        if (Yf) {
#pragma unroll
            for (int m = 0; m < 16; m++) op[half * 16 + m] = acc[m];
        } else {
            unsigned int* op32 = (unsigned int*)op;
#pragma unroll
            for (int m = 0; m < 8; m++) {
                __half2 h0 = __float22half2_rn(upk2(acc[2 * m]));
                __half2 h1 = __float22half2_rn(upk2(acc[2 * m + 1]));
                op32[half * 16 + 2 * m]     = *reinterpret_cast<unsigned int*>(&h0);
                op32[half * 16 + 2 * m + 1] = *reinterpret_cast<unsigned int*>(&h1);
            }
        }
    }
    __syncwarp();

    // coalesced writeback
#pragma unroll 4
    for (int r = 0; r < 32; r++) {
        int row = base + r;
        if (row >= M) break;
        if (Yf) {
            ull v = st[r * 33 + lane];
            *reinterpret_cast<ull*>(Yf + (size_t)row * 64 + 2 * lane) = v;
            if (Yh) {
                __half2 h = __float22half2_rn(upk2(v));
                reinterpret_cast<__half2*>(Yh)[(size_t)row * 32 + lane] = h;
            }
        } else {
            unsigned int v = reinterpret_cast<const unsigned int*>(st)[r * 66 + lane];
            int prow = __shfl_sync(0xffffffffu, permr, r);
            reinterpret_cast<unsigned int*>(Yh)[(size_t)prow * 32 + lane] = v;
        }
    }
}

// ================= aggregation: one warp per dst node, CSR gather =================
__global__ void agg_kernel(const float* __restrict__ cin, const __half* __restrict__ ztab,
                           const float* __restrict__ tp, float* __restrict__ outp)
{
    int gt = blockIdx.x * blockDim.x + threadIdx.x;
    int node = gt >> 5;
    if (node >= NN) return;
    int lane = threadIdx.x & 31;
    float t = __ldg(tp);

    int beg = __ldg(g_off + node);
    int end = __ldg(g_off + node + 1);

    const __half2* eb = reinterpret_cast<const __half2*>(g_e);
    const __half2* zb = reinterpret_cast<const __half2*>(ztab);

    float sex0 = 0.f, sex1 = 0.f, smx0 = 0.f, smx1 = 0.f;

#define ACC(EH, ZH) {                                                   \
        float2 ef = __half22float2(EH), zf = __half22float2(ZH);        \
        float m0 = fmaxf(ef.x + zf.x, 0.f) + 1e-7f;                     \
        float m1 = fmaxf(ef.y + zf.y, 0.f) + 1e-7f;                     \
        float p0 = __expf(m0 * t), p1 = __expf(m1 * t);                 \
        sex0 += p0; smx0 += m0 * p0;                                    \
        sex1 += p1; smx1 += m1 * p1; }

    int j = beg;
    for (; j + 4 <= end; j += 4) {
        int s0 = __ldcs(g_src + j + 0);
        int s1 = __ldcs(g_src + j + 1);
        int s2 = __ldcs(g_src + j + 2);
        int s3 = __ldcs(g_src + j + 3);
        __half2 e0 = __ldcs(eb + (size_t)(j + 0) * 32 + lane);
        __half2 e1 = __ldcs(eb + (size_t)(j + 1) * 32 + lane);
        __half2 e2 = __ldcs(eb + (size_t)(j + 2) * 32 + lane);
        __half2 e3 = __ldcs(eb + (size_t)(j + 3) * 32 + lane);
        __half2 z0 = __ldg(zb + (size_t)s0 * 32 + lane);
        __half2 z1 = __ldg(zb + (size_t)s1 * 32 + lane);
        __half2 z2 = __ldg(zb + (size_t)s2 * 32 + lane);
        __half2 z3 = __ldg(zb + (size_t)s3 * 32 + lane);
        ACC(e0, z0); ACC(e1, z1); ACC(e2, z2); ACC(e3, z3);
    }
    for (; j < end; j++) {
        int s0 = __ldcs(g_src + j);
        __half2 e0 = __ldcs(eb + (size_t)j * 32 + lane);
        __half2 z0 = __ldg(zb + (size_t)s0 * 32 + lane);
        ACC(e0, z0);
    }
#undef ACC

    float2 ci = reinterpret_cast<const float2*>(cin + (size_t)node * 64)[lane];
    float2 o;
    o.x = ci.x + smx0 / (sex0 + 1e-16f);
    o.y = ci.y + smx1 / (sex1 + 1e-16f);
    reinterpret_cast<float2*>(outp + (size_t)node * 64)[lane] = o;
}

// ================= fused node MLP (persistent, 4 nodes/warp, smem-staged operands) =================
__global__ void node_kernel(const float* __restrict__ o_in,
                            const float* __restrict__ h_in,
                            float* __restrict__ h_out,
                            const float* __restrict__ w1,   // [64][128]
                            const float* __restrict__ b1,
                            const float* __restrict__ g1,
                            const float* __restrict__ bb1,
                            const float* __restrict__ w2,   // [128][64]
                            const float* __restrict__ b2,
                            const float* __restrict__ nlg,  // next LN gamma [64]
                            const float* __restrict__ nlb,  // next LN beta  [64]
                            float* __restrict__ z32,
                            __half* __restrict__ z16,
                            int add_residual, int write_h)
{
    extern __shared__ char nsm[];
    float* w1s  = (float*)nsm;                  // 32768 B
    float* w2s  = (float*)(nsm + 32768);        // 32768 B (original [128][64])
    float* b1s  = (float*)(nsm + 65536);        // 512 B
    float* g1s  = (float*)(nsm + 66048);
    float* bb1s = (float*)(nsm + 66560);
    float* b2s  = (float*)(nsm + 67072);        // 256 B -> end 67328
    ull* wbuf   = (ull*)(nsm + 67328);          // 8 warps * 512 ull

    int tid = threadIdx.x;
    for (int i = tid; i < 64 * 128; i += blockDim.x) w1s[i] = w1[i];
    for (int i = tid; i < 128 * 64; i += blockDim.x) w2s[i] = w2[i];
    if (tid < 128) { b1s[tid] = b1[tid]; g1s[tid] = g1[tid]; bb1s[tid] = bb1[tid]; }
    if (tid < 64)  b2s[tid] = b2[tid];
    __syncthreads();

    int lane = tid & 31;
    int winb = tid >> 5;
    ull* ou  = wbuf + winb * 512;        // [n][q2][lane], 256 ull
    ull* z1p = ou + 256;                 // [p][q][lane],  256 ull

    float2 ngg = reinterpret_cast<const float2*>(nlg)[lane];
    float2 nbb = reinterpret_cast<const float2*>(nlb)[lane];
    float4 gv = *reinterpret_cast<const float4*>(g1s + 4 * lane);
    float4 bv = *reinterpret_cast<const float4*>(bb1s + 4 * lane);
    ull bi0, bi1;
    {
        const ull* bp = reinterpret_cast<const ull*>(b1s);
        bi0 = bp[2 * lane]; bi1 = bp[2 * lane + 1];
    }
    float2 b2v = reinterpret_cast<const float2*>(b2s)[lane];
    ull b2d0 = pk2(b2v.x, b2v.x), b2d1 = pk2(b2v.y, b2v.y);

    int warpId = (blockIdx.x * blockDim.x + tid) >> 5;
    int nWarps = (gridDim.x * blockDim.x) >> 5;
    const int nGroups = NN / 4;

    for (int grp = warpId; grp < nGroups; grp += nWarps) {
        int nbase = grp * 4;

        // ---- stage duplicated o into smem ----
        __syncwarp();
#pragma unroll
        for (int n = 0; n < 4; n++) {
            float2 o = reinterpret_cast<const float2*>(o_in + (size_t)(nbase + n) * 64)[lane];
            ou[n * 64 + lane]      = pk2(o.x, o.x);   // k = 2*lane   (q2=0)
            ou[n * 64 + 32 + lane] = pk2(o.y, o.y);   // k = 2*lane+1 (q2=1)
        }
        __syncwarp();

        // ---- matvec1: z[n] = channels 4lane..4lane+3 ----
        ull z0[4], z1a[4];
#pragma unroll
        for (int n = 0; n < 4; n++) { z0[n] = bi0; z1a[n] = bi1; }
#pragma unroll
        for (int q2 = 0; q2 < 2; q2++) {
#pragma unroll 8
            for (int i = 0; i < 32; i++) {
                int k = 2 * i + q2;
                ulonglong2 ww = *reinterpret_cast<const ulonglong2*>(w1s + k * 128 + 4 * lane);
                const ull* oup = ou + q2 * 32 + i;
#pragma unroll
                for (int n = 0; n < 4; n++) {
                    ull a = oup[n * 64];
                    z0[n]  = fma2(a, ww.x, z0[n]);
                    z1a[n] = fma2(a, ww.y, z1a[n]);
                }
            }
        }

        // ---- LayerNorm(128) + ReLU ----
        float zf[4][4];
#pragma unroll
        for (int n = 0; n < 4; n++) {
            float2 lo = upk2(z0[n]), hi = upk2(z1a[n]);
            float ssum = lo.x + lo.y + hi.x + hi.y;
#pragma unroll
            for (int off = 16; off; off >>= 1) ssum += __shfl_xor_sync(0xffffffffu, ssum, off);
            float mu = ssum * (1.f / 128.f);
            float dx = lo.x - mu, dy = lo.y - mu, dz = hi.x - mu, dw = hi.y - mu;
            float sq = dx * dx + dy * dy + dz * dz + dw * dw;
#pragma unroll
            for (int off = 16; off; off >>= 1) sq += __shfl_xor_sync(0xffffffffu, sq, off);
            float rstd = rsqrtf(sq * (1.f / 128.f) + 1e-5f);
            zf[n][0] = fmaxf(dx * rstd * gv.x + bv.x, 0.f);
            zf[n][1] = fmaxf(dy * rstd * gv.y + bv.y, 0.f);
            zf[n][2] = fmaxf(dz * rstd * gv.z + bv.z, 0.f);
            zf[n][3] = fmaxf(dw * rstd * gv.w + bv.w, 0.f);
        }

        // ---- stage z1 node-pair-packed: z1p[p][q][lane], k = 4*lane+q ----
#pragma unroll
        for (int q = 0; q < 4; q++) {
            z1p[q * 32 + lane]       = pk2(zf[0][q], zf[1][q]);
            z1p[128 + q * 32 + lane] = pk2(zf[2][q], zf[3][q]);
        }
        __syncwarp();

        // ---- matvec2: y[j][p] node-packed, j = 2lane,2lane+1 ----
        ull y00 = b2d0, y01 = b2d0, y10 = b2d1, y11 = b2d1;
#pragma unroll
        for (int q = 0; q < 4; q++) {
#pragma unroll 8
            for (int i = 0; i < 32; i++) {
                int k = 4 * i + q;
                float2 wv = *reinterpret_cast<const float2*>(w2s + k * 64 + 2 * lane);
                ull wd0 = pk2(wv.x, wv.x), wd1 = pk2(wv.y, wv.y);
                ull zp0 = z1p[q * 32 + i];
                ull zp1 = z1p[128 + q * 32 + i];
                y00 = fma2(zp0, wd0, y00);
                y01 = fma2(zp1, wd0, y01);
                y10 = fma2(zp0, wd1, y10);
                y11 = fma2(zp1, wd1, y11);
            }
        }

        // unpack y per node: n0=(lo00,lo10) n1=(hi00,hi10) n2=(lo01,lo11) n3=(hi01,hi11)
        float2 a00 = upk2(y00), a10 = upk2(y10), a01 = upk2(y01), a11 = upk2(y11);
        float2 yo[4];
        yo[0] = make_float2(a00.x, a10.x);
        yo[1] = make_float2(a00.y, a10.y);
        yo[2] = make_float2(a01.x, a11.x);
        yo[3] = make_float2(a01.y, a11.y);

        // ---- residual + h store + next-LN epilogue ----
#pragma unroll
        for (int n = 0; n < 4; n++) {
            int node = nbase + n;
            float2 r = yo[n];
            if (add_residual) {
                float2 hv = *reinterpret_cast<const float2*>(h_in + (size_t)node * 64 + 2 * lane);
                r.x += hv.x; r.y += hv.y;
            }
            if (write_h)
                *reinterpret_cast<float2*>(h_out + (size_t)node * 64 + 2 * lane) = r;

            float s = r.x + r.y;
#pragma unroll
            for (int off = 16; off; off >>= 1) s += __shfl_xor_sync(0xffffffffu, s, off);
            float mu = s * (1.f / 64.f);
            float dx = r.x - mu, dy = r.y - mu;
            float q = dx * dx + dy * dy;
#pragma unroll
            for (int off = 16; off; off >>= 1) q += __shfl_xor_sync(0xffffffffu, q, off);
            float rstd = rsqrtf(q * (1.f / 64.f) + 1e-5f);
            float2 zr;
            zr.x = fmaxf(dx * rstd * ngg.x + nbb.x, 0.f);
            zr.y = fmaxf(dy * rstd * ngg.y + nbb.y, 0.f);
            reinterpret_cast<float2*>(z32 + (size_t)node * 64 + 2 * lane)[0] = zr;
            if (z16)
                reinterpret_cast<__half2*>(z16)[(size_t)node * 32 + lane] = __float22half2_rn(zr);
        }
    }
}

// ================= launch =================
extern "C" void kernel_launch(void* const* d_in, const int* in_sizes, int n_in,
                              void* d_out, int out_size)
{
    const float* x   = (const float*)d_in[0];
    const int*   ei  = (const int*)  d_in[1];
    const float* ea  = (const float*)d_in[2];
    const float* enw = (const float*)d_in[3];
    const float* enb = (const float*)d_in[4];
    const float* eew = (const float*)d_in[5];
    const float* eeb = (const float*)d_in[6];
    const float* lng = (const float*)d_in[7];
    const float* lnb = (const float*)d_in[8];
    const float* w1  = (const float*)d_in[9];
    const float* b1  = (const float*)d_in[10];
    const float* mg  = (const float*)d_in[11];
    const float* mb  = (const float*)d_in[12];
    const float* w2  = (const float*)d_in[13];
    const float* b2  = (const float*)d_in[14];
    const float* t   = (const float*)d_in[15];
    float* out = (float*)d_out;

    float *gh, *gz, *go, *gdeg;
    __half *ge, *gzh, *gh16;
    int* gperm;
    cudaGetSymbolAddress((void**)&gh, g_h);
    cudaGetSymbolAddress((void**)&gz, g_z);
    cudaGetSymbolAddress((void**)&go, g_o);
    cudaGetSymbolAddress((void**)&ge, g_e);
    cudaGetSymbolAddress((void**)&gzh, g_zh);
    cudaGetSymbolAddress((void**)&gh16, g_h16);
    cudaGetSymbolAddress((void**)&gperm, g_perm);
    cudaGetSymbolAddress((void**)&gdeg, g_deg);

    const int smem_enc  = 4160 * 4 + 4 * 33 * 32 * 8;     // 50432 B
    const int smem_node = 67328 + 8 * 512 * 8;            // 100096 B
    cudaFuncSetAttribute(enc_kernel,  cudaFuncAttributeMaxDynamicSharedMemorySize, smem_enc);
    cudaFuncSetAttribute(node_kernel, cudaFuncAttributeMaxDynamicSharedMemorySize, smem_node);

    const int warpNodeBlocks = (NN * 32 + 255) / 256;   // agg: 1 warp/node
    const int edgeTB         = (EE + 255) / 256;
    const int persistBlocks  = 296;                     // 2 CTAs/SM (smem-limited)

    // ---- CSR build (deg zero via memset node, not a kernel launch) ----
    cudaMemsetAsync(gdeg, 0, NN * sizeof(int));
    hist_kernel<<<edgeTB, 256>>>(ei);
    scan1_kernel<<<NB, 1024>>>();
    scan2_kernel<<<1, 128>>>();
    scan3_kernel<<<NB, 1024>>>();
    scatter_kernel<<<edgeTB, 256>>>(ei);

    // ---- encoders (edge enc is launch #5 -> gets profiled) ----
    enc_kernel<<<EE / 128, 128, smem_enc>>>(ea, eew, eeb, (float*)nullptr, ge, gperm, EE);
    enc_kernel<<<(NN + 127) / 128, 128, smem_enc>>>(x, enw, enb, gh, gh16, (const int*)nullptr, NN);

    // ---- layers (LN fused into node epilogue) ----
    for (int i = 0; i < 4; i++) {
        const float* cin32  = (i == 0) ? gh   : gz;
        const __half* ztab  = (i == 0) ? gh16 : gzh;
        agg_kernel<<<warpNodeBlocks, 256>>>(cin32, ztab, t + i, go);

        int last = (i == 3);
        const float* nlgp = lng + (last ? 0 : (i + 1)) * 64;
        const float* nlbp = lnb + (last ? 0 : (i + 1)) * 64;
        node_kernel<<<persistBlocks, 256, smem_node>>>(
            go, gh, gh,
            w1 + (size_t)i * 64 * 128, b1 + i * 128,
            mg + i * 128, mb + i * 128,
            w2 + (size_t)i * 128 * 64, b2 + i * 64,
            nlgp, nlbp,
            last ? out : gz, last ? (__half*)nullptr : gzh,
            i > 0 ? 1 : 0, last ? 0 : 1);
    }
}

// round 7
// speedup vs baseline: 2.6915x; 1.3131x over previous
#include <cuda_runtime.h>
#include <cuda_fp16.h>

#define NN 100000
#define EE 1600000
#define NB 98   // ceil(NN/1024)

typedef unsigned long long ull;

// ---------------- scratch (device globals; allocation-free rule) ----------------
__device__ __half g_e[(size_t)EE * 64];      // encoded edge features, fp16, CSR order
__device__ float  g_h[(size_t)NN * 64];      // node state
__device__ float  g_z[(size_t)NN * 64];      // pre-norm conv input (fp32)
__device__ __half g_zh[(size_t)NN * 64];     // gather table (fp16, L2-resident)
__device__ __half g_h16[(size_t)NN * 64];    // fp16 copy of h for layer-0 gather
__device__ float  g_o[(size_t)NN * 64];      // agg output
__device__ int    g_deg[NN];
__device__ int    g_off[NN + 1];
__device__ int    g_cur[NN];
__device__ int    g_src[EE];
__device__ int    g_perm[EE];

// ---------------- packed f32x2 helpers ----------------
__device__ __forceinline__ ull pk2(float x, float y) {
    ull r; asm("mov.b64 %0, {%1, %2};" : "=l"(r) : "f"(x), "f"(y)); return r;
}
__device__ __forceinline__ float2 upk2(ull v) {
    float2 r; asm("mov.b64 {%0, %1}, %2;" : "=f"(r.x), "=f"(r.y) : "l"(v)); return r;
}
__device__ __forceinline__ ull fma2(ull a, ull b, ull c) {
    ull d; asm("fma.rn.f32x2 %0, %1, %2, %3;" : "=l"(d) : "l"(a), "l"(b), "l"(c)); return d;
}

// ================= CSR build =================
__global__ void hist_kernel(const int* __restrict__ ei) {
    int e = blockIdx.x * blockDim.x + threadIdx.x;
    if (e >= EE) return;
    atomicAdd(&g_deg[__ldg(ei + EE + e)], 1);
}

// single-block fused exclusive scan over g_deg -> g_off, g_cur
__global__ void scan_kernel() {
    __shared__ int ws[32];
    __shared__ int stot;
    __shared__ int bcarry;
    int tid = threadIdx.x, lane = tid & 31, wid = tid >> 5;
    if (tid == 0) bcarry = 0;
    __syncthreads();
    for (int c = 0; c < NB; c++) {
        int i = c * 1024 + tid;
        int v = (i < NN) ? g_deg[i] : 0;
        int x = v;
#pragma unroll
        for (int o = 1; o < 32; o <<= 1) {
            int y = __shfl_up_sync(0xffffffffu, x, o);
            if (lane >= o) x += y;
        }
        if (lane == 31) ws[wid] = x;
        int base0 = bcarry;
        __syncthreads();                       // (A)
        if (wid == 0) {
            int y = ws[lane];
            int z = y;
#pragma unroll
            for (int o = 1; o < 32; o <<= 1) {
                int u = __shfl_up_sync(0xffffffffu, z, o);
                if (lane >= o) z += u;
            }
            ws[lane] = z - y;                  // exclusive warp base
            if (lane == 31) stot = z;          // block total
        }
        __syncthreads();                       // (B)
        int excl = base0 + ws[wid] + x - v;
        if (i < NN) { g_off[i] = excl; g_cur[i] = excl; }
        if (tid == 0) bcarry = base0 + stot;
        __syncthreads();                       // (C)
    }
    if (tid == 0) g_off[NN] = bcarry;
}

__global__ void scatter_kernel(const int* __restrict__ ei) {
    int e = blockIdx.x * blockDim.x + threadIdx.x;
    if (e >= EE) return;
    int dst = __ldg(ei + EE + e);
    int slot = atomicAdd(&g_cur[dst], 1);
    g_src[slot] = __ldg(ei + e);
    g_perm[e] = slot;
}

// ================= HMMA edge encoder =================
// Y[perm[r],:] = fp16( X[r,:] @ W + b ), X fp32 [EE,64], tensor-core path.
// 8 warps/block, 16 rows per warp; EE divisible by 128.
__global__ void __launch_bounds__(256) enc_hmma_kernel(
    const float* __restrict__ X, const float* __restrict__ W,
    const float* __restrict__ b, __half* __restrict__ Y,
    const int* __restrict__ perm)
{
    __shared__ __half Wh[64 * 72];      // fp16 W, pitch 72 halfs (144B, 16B-aligned)
    __shared__ float  bsm[64];
    __shared__ __half xs[8][16 * 80];   // per-warp stage, pitch 80 halfs (160B)

    int tid = threadIdx.x;
    for (int i = tid; i < 4096; i += 256)
        Wh[(i >> 6) * 72 + (i & 63)] = __float2half_rn(W[i]);
    if (tid < 64) bsm[tid] = b[tid];
    __syncthreads();

    int lane = tid & 31;
    int w = tid >> 5;
    __half* xw = xs[w];
    int base = (blockIdx.x * 8 + w) * 16;

    int pr = 0;
    if (lane < 16) pr = __ldg(perm + base + lane);

    // ---- stage 16 rows of X as fp16 (coalesced 256B row reads) ----
#pragma unroll
    for (int i = 0; i < 8; i++) {
        int idx = i * 32 + lane;
        int r = idx >> 4, seg = idx & 15;
        float4 v = reinterpret_cast<const float4*>(X)[(size_t)(base + r) * 16 + seg];
        __half2 h0 = __floats2half2_rn(v.x, v.y);
        __half2 h1 = __floats2half2_rn(v.z, v.w);
        uint2 u;
        u.x = *reinterpret_cast<unsigned int*>(&h0);
        u.y = *reinterpret_cast<unsigned int*>(&h1);
        *reinterpret_cast<uint2*>(&xw[r * 80 + seg * 4]) = u;
    }
    __syncwarp();

    // ---- A fragments (16x16 per k-chunk, 4 chunks) ----
    unsigned A[4][4];
    {
        unsigned xbase = (unsigned)__cvta_generic_to_shared(xw);
        int row = (lane & 7) + ((lane >> 3) & 1) * 8;
        int coff = (lane >> 4) * 16;   // bytes
#pragma unroll
        for (int kc = 0; kc < 4; kc++) {
            unsigned addr = xbase + row * 160 + kc * 32 + coff;
            asm volatile("ldmatrix.sync.aligned.m8n8.x4.shared.b16 {%0,%1,%2,%3}, [%4];"
                         : "=r"(A[kc][0]), "=r"(A[kc][1]), "=r"(A[kc][2]), "=r"(A[kc][3])
                         : "r"(addr));
        }
    }
    __syncwarp();   // xw reused for output below

    // ---- compute 8 n-tiles, store to xw (pitch 64 halfs) ----
    unsigned wbase = (unsigned)__cvta_generic_to_shared(Wh);
    int krow = lane & 15;
    int row0 = lane >> 2;
    int col4 = (lane & 3) * 2;
#pragma unroll
    for (int nt = 0; nt < 8; nt++) {
        float c0 = 0.f, c1 = 0.f, c2 = 0.f, c3 = 0.f;
#pragma unroll
        for (int kc = 0; kc < 4; kc++) {
            unsigned b0, b1;
            unsigned addr = wbase + ((kc * 16 + krow) * 72 + nt * 8) * 2;
            asm volatile("ldmatrix.sync.aligned.m8n8.x2.trans.shared.b16 {%0,%1}, [%2];"
                         : "=r"(b0), "=r"(b1) : "r"(addr));
            asm volatile("mma.sync.aligned.m16n8k16.row.col.f32.f16.f16.f32 "
                         "{%0,%1,%2,%3}, {%4,%5,%6,%7}, {%8,%9}, {%0,%1,%2,%3};"
                         : "+f"(c0), "+f"(c1), "+f"(c2), "+f"(c3)
                         : "r"(A[kc][0]), "r"(A[kc][1]), "r"(A[kc][2]), "r"(A[kc][3]),
                           "r"(b0), "r"(b1));
        }
        float2 bf = *reinterpret_cast<const float2*>(bsm + nt * 8 + col4);
        __half2 h01 = __floats2half2_rn(c0 + bf.x, c1 + bf.y);
        __half2 h23 = __floats2half2_rn(c2 + bf.x, c3 + bf.y);
        int colh = nt * 8 + col4;
        *reinterpret_cast<unsigned int*>(&xw[row0 * 64 + colh]) =
            *reinterpret_cast<unsigned int*>(&h01);
        *reinterpret_cast<unsigned int*>(&xw[(row0 + 8) * 64 + colh]) =
            *reinterpret_cast<unsigned int*>(&h23);
    }
    __syncwarp();

    // ---- coalesced perm-scattered writeback (128B per row) ----
#pragma unroll
    for (int i = 0; i < 4; i++) {
        int idx = i * 32 + lane;
        int r = idx >> 3, seg = idx & 7;
        uint4 v = *reinterpret_cast<const uint4*>(&xw[r * 64 + seg * 8]);
        int prow = __shfl_sync(0xffffffffu, pr, r);
        *reinterpret_cast<uint4*>(Y + (size_t)prow * 64 + seg * 8) = v;
    }
}

// ================= fp32 node encoder (small; smem-staged FFMA2) =================
__global__ void __launch_bounds__(128) enc_kernel(
    const float* __restrict__ X, const float* __restrict__ W,
    const float* __restrict__ b,
    float* __restrict__ Yf, __half* __restrict__ Yh, int M)
{
    extern __shared__ float esm[];
    float* Ws = esm;            // 4096 floats
    float* bs = esm + 4096;     // 64
    ull* stage = (ull*)(esm + 4160);   // 4 warps * 32 rows * 33 ull

    int tid = threadIdx.x;
    for (int i = tid; i < 4096; i += blockDim.x) Ws[i] = W[i];
    if (tid < 64) bs[tid] = b[tid];
    __syncthreads();

    int lane = tid & 31;
    int w = tid >> 5;
    ull* st = stage + (size_t)w * (33 * 32);
    int base = blockIdx.x * blockDim.x + w * 32;

#pragma unroll 4
    for (int r = 0; r < 32; r++) {
        int row = base + r;
        if (row < M)
            st[r * 33 + lane] = *reinterpret_cast<const ull*>(X + (size_t)row * 64 + 2 * lane);
    }
    __syncwarp();

    float xr[64];
    {
        const ull* rp = st + lane * 33;
#pragma unroll
        for (int g2 = 0; g2 < 32; g2++) {
            float2 v = upk2(rp[g2]);
            xr[2 * g2] = v.x; xr[2 * g2 + 1] = v.y;
        }
    }
    __syncwarp();

#pragma unroll
    for (int half = 0; half < 2; half++) {
        ull acc[16];
#pragma unroll
        for (int j = 0; j < 16; j++)
            acc[j] = pk2(bs[half * 32 + 2 * j], bs[half * 32 + 2 * j + 1]);

#pragma unroll 8
        for (int k = 0; k < 64; k++) {
            ull xk = pk2(xr[k], xr[k]);
            const ulonglong2* wr = reinterpret_cast<const ulonglong2*>(Ws + k * 64 + half * 32);
#pragma unroll
            for (int m = 0; m < 8; m++) {
                ulonglong2 ww = wr[m];
                acc[2 * m + 0] = fma2(xk, ww.x, acc[2 * m + 0]);
                acc[2 * m + 1] = fma2(xk, ww.y, acc[2 * m + 1]);
            }
        }
        ull* op = st + lane * 33;
#pragma unroll
        for (int m = 0; m < 16; m++) op[half * 16 + m] = acc[m];
    }
    __syncwarp();

#pragma unroll 4
    for (int r = 0; r < 32; r++) {
        int row = base + r;
        if (row >= M) break;
        ull v = st[r * 33 + lane];
        *reinterpret_cast<ull*>(Yf + (size_t)row * 64 + 2 * lane) = v;
        __half2 h = __float22half2_rn(upk2(v));
        reinterpret_cast<__half2*>(Yh)[(size_t)row * 32 + lane] = h;
    }
}

// ================= aggregation: one warp per dst node, CSR gather =================
__global__ void agg_kernel(const float* __restrict__ cin, const __half* __restrict__ ztab,
                           const float* __restrict__ tp, float* __restrict__ outp)
{
    int gt = blockIdx.x * blockDim.x + threadIdx.x;
    int node = gt >> 5;
    if (node >= NN) return;
    int lane = threadIdx.x & 31;
    float t = __ldg(tp);

    int beg = __ldg(g_off + node);
    int end = __ldg(g_off + node + 1);

    const __half2* eb = reinterpret_cast<const __half2*>(g_e);
    const __half2* zb = reinterpret_cast<const __half2*>(ztab);

    float sex0 = 0.f, sex1 = 0.f, smx0 = 0.f, smx1 = 0.f;

#define ACC(EH, ZH) {                                                   \
        float2 ef = __half22float2(EH), zf = __half22float2(ZH);        \
        float m0 = fmaxf(ef.x + zf.x, 0.f) + 1e-7f;                     \
        float m1 = fmaxf(ef.y + zf.y, 0.f) + 1e-7f;                     \
        float p0 = __expf(m0 * t), p1 = __expf(m1 * t);                 \
        sex0 += p0; smx0 += m0 * p0;                                    \
        sex1 += p1; smx1 += m1 * p1; }

    int j = beg;
    for (; j + 4 <= end; j += 4) {
        int s0 = __ldcs(g_src + j + 0);
        int s1 = __ldcs(g_src + j + 1);
        int s2 = __ldcs(g_src + j + 2);
        int s3 = __ldcs(g_src + j + 3);
        __half2 e0 = __ldcs(eb + (size_t)(j + 0) * 32 + lane);
        __half2 e1 = __ldcs(eb + (size_t)(j + 1) * 32 + lane);
        __half2 e2 = __ldcs(eb + (size_t)(j + 2) * 32 + lane);
        __half2 e3 = __ldcs(eb + (size_t)(j + 3) * 32 + lane);
        __half2 z0 = __ldg(zb + (size_t)s0 * 32 + lane);
        __half2 z1 = __ldg(zb + (size_t)s1 * 32 + lane);
        __half2 z2 = __ldg(zb + (size_t)s2 * 32 + lane);
        __half2 z3 = __ldg(zb + (size_t)s3 * 32 + lane);
        ACC(e0, z0); ACC(e1, z1); ACC(e2, z2); ACC(e3, z3);
    }
    for (; j < end; j++) {
        int s0 = __ldcs(g_src + j);
        __half2 e0 = __ldcs(eb + (size_t)j * 32 + lane);
        __half2 z0 = __ldg(zb + (size_t)s0 * 32 + lane);
        ACC(e0, z0);
    }
#undef ACC

    float2 ci = reinterpret_cast<const float2*>(cin + (size_t)node * 64)[lane];
    float2 o;
    o.x = ci.x + smx0 / (sex0 + 1e-16f);
    o.y = ci.y + smx1 / (sex1 + 1e-16f);
    reinterpret_cast<float2*>(outp + (size_t)node * 64)[lane] = o;
}

// ================= fused node MLP (persistent, 4 nodes/warp, smem-staged operands) =================
__global__ void node_kernel(const float* __restrict__ o_in,
                            const float* __restrict__ h_in,
                            float* __restrict__ h_out,
                            const float* __restrict__ w1,   // [64][128]
                            const float* __restrict__ b1,
                            const float* __restrict__ g1,
                            const float* __restrict__ bb1,
                            const float* __restrict__ w2,   // [128][64]
                            const float* __restrict__ b2,
                            const float* __restrict__ nlg,
                            const float* __restrict__ nlb,
                            float* __restrict__ z32,
                            __half* __restrict__ z16,
                            int add_residual, int write_h)
{
    extern __shared__ char nsm[];
    float* w1s  = (float*)nsm;
    float* w2s  = (float*)(nsm + 32768);
    float* b1s  = (float*)(nsm + 65536);
    float* g1s  = (float*)(nsm + 66048);
    float* bb1s = (float*)(nsm + 66560);
    float* b2s  = (float*)(nsm + 67072);
    ull* wbuf   = (ull*)(nsm + 67328);

    int tid = threadIdx.x;
    for (int i = tid; i < 64 * 128; i += blockDim.x) w1s[i] = w1[i];
    for (int i = tid; i < 128 * 64; i += blockDim.x) w2s[i] = w2[i];
    if (tid < 128) { b1s[tid] = b1[tid]; g1s[tid] = g1[tid]; bb1s[tid] = bb1[tid]; }
    if (tid < 64)  b2s[tid] = b2[tid];
    __syncthreads();

    int lane = tid & 31;
    int winb = tid >> 5;
    ull* ou  = wbuf + winb * 512;
    ull* z1p = ou + 256;

    float2 ngg = reinterpret_cast<const float2*>(nlg)[lane];
    float2 nbb = reinterpret_cast<const float2*>(nlb)[lane];
    float4 gv = *reinterpret_cast<const float4*>(g1s + 4 * lane);
    float4 bv = *reinterpret_cast<const float4*>(bb1s + 4 * lane);
    ull bi0, bi1;
    {
        const ull* bp = reinterpret_cast<const ull*>(b1s);
        bi0 = bp[2 * lane]; bi1 = bp[2 * lane + 1];
    }
    float2 b2v = reinterpret_cast<const float2*>(b2s)[lane];
    ull b2d0 = pk2(b2v.x, b2v.x), b2d1 = pk2(b2v.y, b2v.y);

    int warpId = (blockIdx.x * blockDim.x + tid) >> 5;
    int nWarps = (gridDim.x * blockDim.x) >> 5;
    const int nGroups = NN / 4;

    for (int grp = warpId; grp < nGroups; grp += nWarps) {
        int nbase = grp * 4;

        __syncwarp();
#pragma unroll
        for (int n = 0; n < 4; n++) {
            float2 o = reinterpret_cast<const float2*>(o_in + (size_t)(nbase + n) * 64)[lane];
            ou[n * 64 + lane]      = pk2(o.x, o.x);
            ou[n * 64 + 32 + lane] = pk2(o.y, o.y);
        }
        __syncwarp();

        ull z0[4], z1a[4];
#pragma unroll
        for (int n = 0; n < 4; n++) { z0[n] = bi0; z1a[n] = bi1; }
#pragma unroll
        for (int q2 = 0; q2 < 2; q2++) {
#pragma unroll 8
            for (int i = 0; i < 32; i++) {
                int k = 2 * i + q2;
                ulonglong2 ww = *reinterpret_cast<const ulonglong2*>(w1s + k * 128 + 4 * lane);
                const ull* oup = ou + q2 * 32 + i;
#pragma unroll
                for (int n = 0; n < 4; n++) {
                    ull a = oup[n * 64];
                    z0[n]  = fma2(a, ww.x, z0[n]);
                    z1a[n] = fma2(a, ww.y, z1a[n]);
                }
            }
        }

        float zf[4][4];
#pragma unroll
        for (int n = 0; n < 4; n++) {
            float2 lo = upk2(z0[n]), hi = upk2(z1a[n]);
            float ssum = lo.x + lo.y + hi.x + hi.y;
#pragma unroll
            for (int off = 16; off; off >>= 1) ssum += __shfl_xor_sync(0xffffffffu, ssum, off);
            float mu = ssum * (1.f / 128.f);
            float dx = lo.x - mu, dy = lo.y - mu, dz = hi.x - mu, dw = hi.y - mu;
            float sq = dx * dx + dy * dy + dz * dz + dw * dw;
#pragma unroll
            for (int off = 16; off; off >>= 1) sq += __shfl_xor_sync(0xffffffffu, sq, off);
            float rstd = rsqrtf(sq * (1.f / 128.f) + 1e-5f);
            zf[n][0] = fmaxf(dx * rstd * gv.x + bv.x, 0.f);
            zf[n][1] = fmaxf(dy * rstd * gv.y + bv.y, 0.f);
            zf[n][2] = fmaxf(dz * rstd * gv.z + bv.z, 0.f);
            zf[n][3] = fmaxf(dw * rstd * gv.w + bv.w, 0.f);
        }

#pragma unroll
        for (int q = 0; q < 4; q++) {
            z1p[q * 32 + lane]       = pk2(zf[0][q], zf[1][q]);
            z1p[128 + q * 32 + lane] = pk2(zf[2][q], zf[3][q]);
        }
        __syncwarp();

        ull y00 = b2d0, y01 = b2d0, y10 = b2d1, y11 = b2d1;
#pragma unroll
        for (int q = 0; q < 4; q++) {
#pragma unroll 8
            for (int i = 0; i < 32; i++) {
                int k = 4 * i + q;
                float2 wv = *reinterpret_cast<const float2*>(w2s + k * 64 + 2 * lane);
                ull wd0 = pk2(wv.x, wv.x), wd1 = pk2(wv.y, wv.y);
                ull zp0 = z1p[q * 32 + i];
                ull zp1 = z1p[128 + q * 32 + i];
                y00 = fma2(zp0, wd0, y00);
                y01 = fma2(zp1, wd0, y01);
                y10 = fma2(zp0, wd1, y10);
                y11 = fma2(zp1, wd1, y11);
            }
        }

        float2 a00 = upk2(y00), a10 = upk2(y10), a01 = upk2(y01), a11 = upk2(y11);
        float2 yo[4];
        yo[0] = make_float2(a00.x, a10.x);
        yo[1] = make_float2(a00.y, a10.y);
        yo[2] = make_float2(a01.x, a11.x);
        yo[3] = make_float2(a01.y, a11.y);

#pragma unroll
        for (int n = 0; n < 4; n++) {
            int node = nbase + n;
            float2 r = yo[n];
            if (add_residual) {
                float2 hv = *reinterpret_cast<const float2*>(h_in + (size_t)node * 64 + 2 * lane);
                r.x += hv.x; r.y += hv.y;
            }
            if (write_h)
                *reinterpret_cast<float2*>(h_out + (size_t)node * 64 + 2 * lane) = r;

            float s = r.x + r.y;
#pragma unroll
            for (int off = 16; off; off >>= 1) s += __shfl_xor_sync(0xffffffffu, s, off);
            float mu = s * (1.f / 64.f);
            float dx = r.x - mu, dy = r.y - mu;
            float q = dx * dx + dy * dy;
#pragma unroll
            for (int off = 16; off; off >>= 1) q += __shfl_xor_sync(0xffffffffu, q, off);
            float rstd = rsqrtf(q * (1.f / 64.f) + 1e-5f);
            float2 zr;
            zr.x = fmaxf(dx * rstd * ngg.x + nbb.x, 0.f);
            zr.y = fmaxf(dy * rstd * ngg.y + nbb.y, 0.f);
            reinterpret_cast<float2*>(z32 + (size_t)node * 64 + 2 * lane)[0] = zr;
            if (z16)
                reinterpret_cast<__half2*>(z16)[(size_t)node * 32 + lane] = __float22half2_rn(zr);
        }
    }
}

// ================= launch =================
extern "C" void kernel_launch(void* const* d_in, const int* in_sizes, int n_in,
                              void* d_out, int out_size)
{
    const float* x   = (const float*)d_in[0];
    const int*   ei  = (const int*)  d_in[1];
    const float* ea  = (const float*)d_in[2];
    const float* enw = (const float*)d_in[3];
    const float* enb = (const float*)d_in[4];
    const float* eew = (const float*)d_in[5];
    const float* eeb = (const float*)d_in[6];
    const float* lng = (const float*)d_in[7];
    const float* lnb = (const float*)d_in[8];
    const float* w1  = (const float*)d_in[9];
    const float* b1  = (const float*)d_in[10];
    const float* mg  = (const float*)d_in[11];
    const float* mb  = (const float*)d_in[12];
    const float* w2  = (const float*)d_in[13];
    const float* b2  = (const float*)d_in[14];
    const float* t   = (const float*)d_in[15];
    float* out = (float*)d_out;

    float *gh, *gz, *go, *gdeg;
    __half *ge, *gzh, *gh16;
    int* gperm;
    cudaGetSymbolAddress((void**)&gh, g_h);
    cudaGetSymbolAddress((void**)&gz, g_z);
    cudaGetSymbolAddress((void**)&go, g_o);
    cudaGetSymbolAddress((void**)&ge, g_e);
    cudaGetSymbolAddress((void**)&gzh, g_zh);
    cudaGetSymbolAddress((void**)&gh16, g_h16);
    cudaGetSymbolAddress((void**)&gperm, g_perm);
    cudaGetSymbolAddress((void**)&gdeg, g_deg);

    const int smem_enc  = 4160 * 4 + 4 * 33 * 32 * 8;     // 50432 B
    const int smem_node = 67328 + 8 * 512 * 8;            // 100096 B
    cudaFuncSetAttribute(enc_kernel,  cudaFuncAttributeMaxDynamicSharedMemorySize, smem_enc);
    cudaFuncSetAttribute(node_kernel, cudaFuncAttributeMaxDynamicSharedMemorySize, smem_node);

    const int warpNodeBlocks = (NN * 32 + 255) / 256;
    const int edgeTB         = (EE + 255) / 256;
    const int persistBlocks  = 296;

    // ---- CSR build (3 kernels; memset not a kernel launch) ----
    cudaMemsetAsync(gdeg, 0, NN * sizeof(int));
    hist_kernel<<<edgeTB, 256>>>(ei);          // launch 1
    scan_kernel<<<1, 1024>>>();                // launch 2
    scatter_kernel<<<edgeTB, 256>>>(ei);       // launch 3

    // ---- encoders (HMMA edge encoder is launch 4 -> profiled) ----
    enc_hmma_kernel<<<EE / 128, 256>>>(ea, eew, eeb, ge, gperm);            // launch 4
    enc_kernel<<<(NN + 127) / 128, 128, smem_enc>>>(x, enw, enb, gh, gh16, NN);

    // ---- layers (LN fused into node epilogue) ----
    for (int i = 0; i < 4; i++) {
        const float* cin32  = (i == 0) ? gh   : gz;
        const __half* ztab  = (i == 0) ? gh16 : gzh;
        agg_kernel<<<warpNodeBlocks, 256>>>(cin32, ztab, t + i, go);

        int last = (i == 3);
        const float* nlgp = lng + (last ? 0 : (i + 1)) * 64;
        const float* nlbp = lnb + (last ? 0 : (i + 1)) * 64;
        node_kernel<<<persistBlocks, 256, smem_node>>>(
            go, gh, gh,
            w1 + (size_t)i * 64 * 128, b1 + i * 128,
            mg + i * 128, mb + i * 128,
            w2 + (size_t)i * 128 * 64, b2 + i * 64,
            nlgp, nlbp,
            last ? out : gz, last ? (__half*)nullptr : gzh,
            i > 0 ? 1 : 0, last ? 0 : 1);
    }
}

// round 8
// speedup vs baseline: 3.9570x; 1.4702x over previous
#include <cuda_runtime.h>
#include <cuda_fp16.h>

#define NN 100000
#define EE 1600000
#define NB 98   // ceil(NN/1024)

typedef unsigned long long ull;

// ---------------- scratch ----------------
__device__ __half g_e[(size_t)EE * 64];      // encoded edge features, fp16, CSR order
__device__ float  g_h[(size_t)NN * 64];      // node state
__device__ float  g_z[(size_t)NN * 64];      // pre-norm conv input (fp32, agg ci)
__device__ __half g_zh[(size_t)NN * 64];     // gather table (fp16)
__device__ __half g_h16[(size_t)NN * 64];    // fp16 h for layer-0 gather
__device__ __half g_o16[(size_t)NN * 64];    // agg output, fp16 (MLP input)
__device__ int    g_deg[NN];
__device__ int    g_off[NN + 1];
__device__ int    g_cur[NN];
__device__ int    g_src[EE];
__device__ int    g_perm[EE];

// ---------------- packed f32x2 helpers ----------------
__device__ __forceinline__ ull pk2(float x, float y) {
    ull r; asm("mov.b64 %0, {%1, %2};" : "=l"(r) : "f"(x), "f"(y)); return r;
}
__device__ __forceinline__ float2 upk2(ull v) {
    float2 r; asm("mov.b64 {%0, %1}, %2;" : "=f"(r.x), "=f"(r.y) : "l"(v)); return r;
}
__device__ __forceinline__ ull fma2(ull a, ull b, ull c) {
    ull d; asm("fma.rn.f32x2 %0, %1, %2, %3;" : "=l"(d) : "l"(a), "l"(b), "l"(c)); return d;
}
__device__ __forceinline__ void mma16816(float& c0, float& c1, float& c2, float& c3,
                                         unsigned a0, unsigned a1, unsigned a2, unsigned a3,
                                         unsigned b0, unsigned b1) {
    asm volatile("mma.sync.aligned.m16n8k16.row.col.f32.f16.f16.f32 "
                 "{%0,%1,%2,%3}, {%4,%5,%6,%7}, {%8,%9}, {%0,%1,%2,%3};"
                 : "+f"(c0), "+f"(c1), "+f"(c2), "+f"(c3)
                 : "r"(a0), "r"(a1), "r"(a2), "r"(a3), "r"(b0), "r"(b1));
}

// ================= CSR build =================
__global__ void hist_kernel(const int* __restrict__ ei) {
    int e = blockIdx.x * blockDim.x + threadIdx.x;
    if (e >= EE) return;
    atomicAdd(&g_deg[__ldg(ei + EE + e)], 1);
}

__global__ void scan_kernel() {
    __shared__ int ws[32];
    __shared__ int stot;
    __shared__ int bcarry;
    int tid = threadIdx.x, lane = tid & 31, wid = tid >> 5;
    if (tid == 0) bcarry = 0;
    __syncthreads();
    for (int c = 0; c < NB; c++) {
        int i = c * 1024 + tid;
        int v = (i < NN) ? g_deg[i] : 0;
        int x = v;
#pragma unroll
        for (int o = 1; o < 32; o <<= 1) {
            int y = __shfl_up_sync(0xffffffffu, x, o);
            if (lane >= o) x += y;
        }
        if (lane == 31) ws[wid] = x;
        int base0 = bcarry;
        __syncthreads();
        if (wid == 0) {
            int y = ws[lane];
            int z = y;
#pragma unroll
            for (int o = 1; o < 32; o <<= 1) {
                int u = __shfl_up_sync(0xffffffffu, z, o);
                if (lane >= o) z += u;
            }
            ws[lane] = z - y;
            if (lane == 31) stot = z;
        }
        __syncthreads();
        int excl = base0 + ws[wid] + x - v;
        if (i < NN) { g_off[i] = excl; g_cur[i] = excl; }
        if (tid == 0) bcarry = base0 + stot;
        __syncthreads();
    }
    if (tid == 0) g_off[NN] = bcarry;
}

__global__ void scatter_kernel(const int* __restrict__ ei) {
    int e = blockIdx.x * blockDim.x + threadIdx.x;
    if (e >= EE) return;
    int dst = __ldg(ei + EE + e);
    int slot = atomicAdd(&g_cur[dst], 1);
    g_src[slot] = __ldg(ei + e);
    g_perm[e] = slot;
}

// ================= HMMA edge encoder (persistent; W fragments in registers) =================
__global__ void __launch_bounds__(256) enc_hmma_kernel(
    const float* __restrict__ X, const float* __restrict__ W,
    const float* __restrict__ b, __half* __restrict__ Y,
    const int* __restrict__ perm)
{
    __shared__ __half Wh[64 * 72];
    __shared__ float  bsm[64];
    __shared__ __half xs[8][16 * 80];

    int tid = threadIdx.x;
    for (int i = tid; i < 4096; i += 256)
        Wh[(i >> 6) * 72 + (i & 63)] = __float2half_rn(W[i]);
    if (tid < 64) bsm[tid] = b[tid];
    __syncthreads();

    int lane = tid & 31;
    int w = tid >> 5;
    __half* xw = xs[w];

    // ---- load all B fragments once (8 nt x 4 kc) ----
    unsigned Bf[8][4][2];
    {
        unsigned wbase = (unsigned)__cvta_generic_to_shared(Wh);
        int krow = lane & 15;
#pragma unroll
        for (int nt = 0; nt < 8; nt++)
#pragma unroll
            for (int kc = 0; kc < 4; kc++) {
                unsigned addr = wbase + ((kc * 16 + krow) * 72 + nt * 8) * 2;
                asm volatile("ldmatrix.sync.aligned.m8n8.x2.trans.shared.b16 {%0,%1}, [%2];"
                             : "=r"(Bf[nt][kc][0]), "=r"(Bf[nt][kc][1]) : "r"(addr));
            }
    }

    int row0 = lane >> 2;
    int col4 = (lane & 3) * 2;
    float2 bfr[8];
#pragma unroll
    for (int nt = 0; nt < 8; nt++)
        bfr[nt] = *reinterpret_cast<const float2*>(bsm + nt * 8 + col4);

    unsigned xbase = (unsigned)__cvta_generic_to_shared(xw);
    int arow = (lane & 7) + ((lane >> 3) & 1) * 8;
    int acoff = (lane >> 4) * 16;

    int wG = blockIdx.x * 8 + w;
    const int nChunks = EE / 16;       // 100000
    const int strideW = 296 * 8;

    for (int c = wG; c < nChunks; c += strideW) {
        int base = c * 16;
        int pr = 0;
        if (lane < 16) pr = __ldg(perm + base + lane);

        // stage 16 rows fp32 -> fp16
#pragma unroll
        for (int i = 0; i < 8; i++) {
            int idx = i * 32 + lane;
            int r = idx >> 4, seg = idx & 15;
            float4 v = reinterpret_cast<const float4*>(X)[(size_t)(base + r) * 16 + seg];
            __half2 h0 = __floats2half2_rn(v.x, v.y);
            __half2 h1 = __floats2half2_rn(v.z, v.w);
            uint2 u;
            u.x = *reinterpret_cast<unsigned int*>(&h0);
            u.y = *reinterpret_cast<unsigned int*>(&h1);
            *reinterpret_cast<uint2*>(&xw[r * 80 + seg * 4]) = u;
        }
        __syncwarp();

        unsigned A[4][4];
#pragma unroll
        for (int kc = 0; kc < 4; kc++) {
            unsigned addr = xbase + arow * 160 + kc * 32 + acoff;
            asm volatile("ldmatrix.sync.aligned.m8n8.x4.shared.b16 {%0,%1,%2,%3}, [%4];"
                         : "=r"(A[kc][0]), "=r"(A[kc][1]), "=r"(A[kc][2]), "=r"(A[kc][3])
                         : "r"(addr));
        }
        __syncwarp();

#pragma unroll
        for (int nt = 0; nt < 8; nt++) {
            float c0 = 0.f, c1 = 0.f, c2 = 0.f, c3 = 0.f;
#pragma unroll
            for (int kc = 0; kc < 4; kc++)
                mma16816(c0, c1, c2, c3, A[kc][0], A[kc][1], A[kc][2], A[kc][3],
                         Bf[nt][kc][0], Bf[nt][kc][1]);
            __half2 h01 = __floats2half2_rn(c0 + bfr[nt].x, c1 + bfr[nt].y);
            __half2 h23 = __floats2half2_rn(c2 + bfr[nt].x, c3 + bfr[nt].y);
            int colh = nt * 8 + col4;
            *reinterpret_cast<unsigned int*>(&xw[row0 * 64 + colh]) =
                *reinterpret_cast<unsigned int*>(&h01);
            *reinterpret_cast<unsigned int*>(&xw[(row0 + 8) * 64 + colh]) =
                *reinterpret_cast<unsigned int*>(&h23);
        }
        __syncwarp();

#pragma unroll
        for (int i = 0; i < 4; i++) {
            int idx = i * 32 + lane;
            int r = idx >> 3, seg = idx & 7;
            uint4 v = *reinterpret_cast<const uint4*>(&xw[r * 64 + seg * 8]);
            int prow = __shfl_sync(0xffffffffu, pr, r);
            *reinterpret_cast<uint4*>(Y + (size_t)prow * 64 + seg * 8) = v;
        }
        __syncwarp();
    }
}

// ================= fp32 node encoder (FFMA2; writes gh fp32 + gh16) =================
__global__ void __launch_bounds__(128) enc_kernel(
    const float* __restrict__ X, const float* __restrict__ W,
    const float* __restrict__ b,
    float* __restrict__ Yf, __half* __restrict__ Yh, int M)
{
    extern __shared__ float esm[];
    float* Ws = esm;
    float* bs = esm + 4096;
    ull* stage = (ull*)(esm + 4160);

    int tid = threadIdx.x;
    for (int i = tid; i < 4096; i += blockDim.x) Ws[i] = W[i];
    if (tid < 64) bs[tid] = b[tid];
    __syncthreads();

    int lane = tid & 31;
    int w = tid >> 5;
    ull* st = stage + (size_t)w * (33 * 32);
    int base = blockIdx.x * blockDim.x + w * 32;

#pragma unroll 4
    for (int r = 0; r < 32; r++) {
        int row = base + r;
        if (row < M)
            st[r * 33 + lane] = *reinterpret_cast<const ull*>(X + (size_t)row * 64 + 2 * lane);
    }
    __syncwarp();

    float xr[64];
    {
        const ull* rp = st + lane * 33;
#pragma unroll
        for (int g2 = 0; g2 < 32; g2++) {
            float2 v = upk2(rp[g2]);
            xr[2 * g2] = v.x; xr[2 * g2 + 1] = v.y;
        }
    }
    __syncwarp();

#pragma unroll
    for (int half = 0; half < 2; half++) {
        ull acc[16];
#pragma unroll
        for (int j = 0; j < 16; j++)
            acc[j] = pk2(bs[half * 32 + 2 * j], bs[half * 32 + 2 * j + 1]);

#pragma unroll 8
        for (int k = 0; k < 64; k++) {
            ull xk = pk2(xr[k], xr[k]);
            const ulonglong2* wr = reinterpret_cast<const ulonglong2*>(Ws + k * 64 + half * 32);
#pragma unroll
            for (int m = 0; m < 8; m++) {
                ulonglong2 ww = wr[m];
                acc[2 * m + 0] = fma2(xk, ww.x, acc[2 * m + 0]);
                acc[2 * m + 1] = fma2(xk, ww.y, acc[2 * m + 1]);
            }
        }
        ull* op = st + lane * 33;
#pragma unroll
        for (int m = 0; m < 16; m++) op[half * 16 + m] = acc[m];
    }
    __syncwarp();

#pragma unroll 4
    for (int r = 0; r < 32; r++) {
        int row = base + r;
        if (row >= M) break;
        ull v = st[r * 33 + lane];
        *reinterpret_cast<ull*>(Yf + (size_t)row * 64 + 2 * lane) = v;
        __half2 h = __float22half2_rn(upk2(v));
        reinterpret_cast<__half2*>(Yh)[(size_t)row * 32 + lane] = h;
    }
}

// ================= aggregation: one warp per dst node, fp16 output =================
__global__ void agg_kernel(const float* __restrict__ cin, const __half* __restrict__ ztab,
                           const float* __restrict__ tp, __half* __restrict__ outp)
{
    int gt = blockIdx.x * blockDim.x + threadIdx.x;
    int node = gt >> 5;
    if (node >= NN) return;
    int lane = threadIdx.x & 31;
    float t = __ldg(tp);

    int beg = __ldg(g_off + node);
    int end = __ldg(g_off + node + 1);

    const __half2* eb = reinterpret_cast<const __half2*>(g_e);
    const __half2* zb = reinterpret_cast<const __half2*>(ztab);

    float sex0 = 0.f, sex1 = 0.f, smx0 = 0.f, smx1 = 0.f;

#define ACC(EH, ZH) {                                                   \
        float2 ef = __half22float2(EH), zf = __half22float2(ZH);        \
        float m0 = fmaxf(ef.x + zf.x, 0.f) + 1e-7f;                     \
        float m1 = fmaxf(ef.y + zf.y, 0.f) + 1e-7f;                     \
        float p0 = __expf(m0 * t), p1 = __expf(m1 * t);                 \
        sex0 += p0; smx0 += m0 * p0;                                    \
        sex1 += p1; smx1 += m1 * p1; }

    int j = beg;
    for (; j + 4 <= end; j += 4) {
        int s0 = __ldcs(g_src + j + 0);
        int s1 = __ldcs(g_src + j + 1);
        int s2 = __ldcs(g_src + j + 2);
        int s3 = __ldcs(g_src + j + 3);
        __half2 e0 = __ldcs(eb + (size_t)(j + 0) * 32 + lane);
        __half2 e1 = __ldcs(eb + (size_t)(j + 1) * 32 + lane);
        __half2 e2 = __ldcs(eb + (size_t)(j + 2) * 32 + lane);
        __half2 e3 = __ldcs(eb + (size_t)(j + 3) * 32 + lane);
        __half2 z0 = __ldg(zb + (size_t)s0 * 32 + lane);
        __half2 z1 = __ldg(zb + (size_t)s1 * 32 + lane);
        __half2 z2 = __ldg(zb + (size_t)s2 * 32 + lane);
        __half2 z3 = __ldg(zb + (size_t)s3 * 32 + lane);
        ACC(e0, z0); ACC(e1, z1); ACC(e2, z2); ACC(e3, z3);
    }
    for (; j < end; j++) {
        int s0 = __ldcs(g_src + j);
        __half2 e0 = __ldcs(eb + (size_t)j * 32 + lane);
        __half2 z0 = __ldg(zb + (size_t)s0 * 32 + lane);
        ACC(e0, z0);
    }
#undef ACC

    float2 ci = reinterpret_cast<const float2*>(cin + (size_t)node * 64)[lane];
    float2 o;
    o.x = ci.x + smx0 / (sex0 + 1e-16f);
    o.y = ci.y + smx1 / (sex1 + 1e-16f);
    reinterpret_cast<__half2*>(outp)[(size_t)node * 32 + lane] = __float22half2_rn(o);
}

// ================= HMMA node MLP: one warp = 16 nodes =================
// h_new = (res? h_in:0) + MLP(o16); epilogue r = relu(LN64(h_new)) -> z32 (+z16)
__global__ void __launch_bounds__(256) node_hmma_kernel(
    const __half* __restrict__ o16,
    const float* __restrict__ h_in,
    float* __restrict__ h_out,
    const float* __restrict__ w1,   // [64][128]
    const float* __restrict__ b1,
    const float* __restrict__ g1,
    const float* __restrict__ bb1,
    const float* __restrict__ w2,   // [128][64]
    const float* __restrict__ b2,
    const float* __restrict__ nlg,
    const float* __restrict__ nlb,
    float* __restrict__ z32,
    __half* __restrict__ z16,
    int add_residual, int write_h)
{
    extern __shared__ char sm[];
    __half* w1h = (__half*)sm;                      // 64 x 136 halfs = 17408 B
    __half* w2h = (__half*)(sm + 17408);            // 128 x 72 halfs = 18432 B
    __half* ows = (__half*)(sm + 35840);            // 8 warps x 16 x 72 halfs
    float* b1f  = (float*)(sm + 54272);             // 128
    float* g1f  = (float*)(sm + 54784);             // 128
    float* bb1f = (float*)(sm + 55296);             // 128
    float* b2f  = (float*)(sm + 55808);             // 64
    float* nlgf = (float*)(sm + 56064);             // 64
    float* nlbf = (float*)(sm + 56320);             // 64  (end 56576)

    int tid = threadIdx.x;
    for (int i = tid; i < 8192; i += 256)
        w1h[(i >> 7) * 136 + (i & 127)] = __float2half_rn(w1[i]);
    for (int i = tid; i < 8192; i += 256)
        w2h[(i >> 6) * 72 + (i & 63)] = __float2half_rn(w2[i]);
    if (tid < 128) { b1f[tid] = b1[tid]; g1f[tid] = g1[tid]; bb1f[tid] = bb1[tid]; }
    if (tid < 64)  { b2f[tid] = b2[tid]; nlgf[tid] = nlg[tid]; nlbf[tid] = nlb[tid]; }
    __syncthreads();

    int lane = tid & 31;
    int w = tid >> 5;
    int wG = blockIdx.x * 8 + w;
    if (wG >= NN / 16) return;
    int nbase = wG * 16;

    __half* ow = ows + w * (16 * 72);

    // ---- stage o16 rows (16 x 128B, coalesced) ----
#pragma unroll
    for (int i = 0; i < 4; i++) {
        int idx = i * 32 + lane;
        int r = idx >> 3, seg = idx & 7;
        uint4 v = *reinterpret_cast<const uint4*>(o16 + (size_t)(nbase + r) * 64 + seg * 8);
        *reinterpret_cast<uint4*>(&ow[r * 72 + seg * 8]) = v;
    }
    __syncwarp();

    // ---- A1 fragments ----
    unsigned A1[4][4];
    {
        unsigned obase = (unsigned)__cvta_generic_to_shared(ow);
        int arow = (lane & 7) + ((lane >> 3) & 1) * 8;
        int acoff = (lane >> 4) * 16;
#pragma unroll
        for (int kc = 0; kc < 4; kc++) {
            unsigned addr = obase + arow * 144 + kc * 32 + acoff;
            asm volatile("ldmatrix.sync.aligned.m8n8.x4.shared.b16 {%0,%1,%2,%3}, [%4];"
                         : "=r"(A1[kc][0]), "=r"(A1[kc][1]), "=r"(A1[kc][2]), "=r"(A1[kc][3])
                         : "r"(addr));
        }
    }

    unsigned w1base = (unsigned)__cvta_generic_to_shared(w1h);
    unsigned w2base = (unsigned)__cvta_generic_to_shared(w2h);
    int krow = lane & 15;
    int t4 = lane & 3;
    int grow = lane >> 2;

    // ---- matvec1: C[16 nt][4] ----
    float c[16][4];
#pragma unroll
    for (int nt = 0; nt < 16; nt++) {
        c[nt][0] = c[nt][1] = c[nt][2] = c[nt][3] = 0.f;
#pragma unroll
        for (int kc = 0; kc < 4; kc++) {
            unsigned b0, b1r;
            unsigned addr = w1base + ((kc * 16 + krow) * 136 + nt * 8) * 2;
            asm volatile("ldmatrix.sync.aligned.m8n8.x2.trans.shared.b16 {%0,%1}, [%2];"
                         : "=r"(b0), "=r"(b1r) : "r"(addr));
            mma16816(c[nt][0], c[nt][1], c[nt][2], c[nt][3],
                     A1[kc][0], A1[kc][1], A1[kc][2], A1[kc][3], b0, b1r);
        }
    }

    // ---- bias + LN(128) + ReLU, pack A2 frags ----
    float sumA = 0.f, sumB = 0.f;
#pragma unroll
    for (int nt = 0; nt < 16; nt++) {
        float2 bv = *reinterpret_cast<const float2*>(b1f + nt * 8 + 2 * t4);
        c[nt][0] += bv.x; c[nt][1] += bv.y;
        c[nt][2] += bv.x; c[nt][3] += bv.y;
        sumA += c[nt][0] + c[nt][1];
        sumB += c[nt][2] + c[nt][3];
    }
    sumA += __shfl_xor_sync(0xffffffffu, sumA, 1);
    sumA += __shfl_xor_sync(0xffffffffu, sumA, 2);
    sumB += __shfl_xor_sync(0xffffffffu, sumB, 1);
    sumB += __shfl_xor_sync(0xffffffffu, sumB, 2);
    float muA = sumA * (1.f / 128.f), muB = sumB * (1.f / 128.f);
    float sqA = 0.f, sqB = 0.f;
#pragma unroll
    for (int nt = 0; nt < 16; nt++) {
        float d0 = c[nt][0] - muA, d1 = c[nt][1] - muA;
        float d2 = c[nt][2] - muB, d3 = c[nt][3] - muB;
        sqA += d0 * d0 + d1 * d1;
        sqB += d2 * d2 + d3 * d3;
    }
    sqA += __shfl_xor_sync(0xffffffffu, sqA, 1);
    sqA += __shfl_xor_sync(0xffffffffu, sqA, 2);
    sqB += __shfl_xor_sync(0xffffffffu, sqB, 1);
    sqB += __shfl_xor_sync(0xffffffffu, sqB, 2);
    float rA = rsqrtf(sqA * (1.f / 128.f) + 1e-5f);
    float rB = rsqrtf(sqB * (1.f / 128.f) + 1e-5f);

    unsigned A2[8][4];
#pragma unroll
    for (int kc2 = 0; kc2 < 8; kc2++) {
#pragma unroll
        for (int half = 0; half < 2; half++) {
            int nt = 2 * kc2 + half;
            float2 gvv = *reinterpret_cast<const float2*>(g1f + nt * 8 + 2 * t4);
            float2 bvv = *reinterpret_cast<const float2*>(bb1f + nt * 8 + 2 * t4);
            float z0 = fmaxf((c[nt][0] - muA) * rA * gvv.x + bvv.x, 0.f);
            float z1 = fmaxf((c[nt][1] - muA) * rA * gvv.y + bvv.y, 0.f);
            float z2 = fmaxf((c[nt][2] - muB) * rB * gvv.x + bvv.x, 0.f);
            float z3 = fmaxf((c[nt][3] - muB) * rB * gvv.y + bvv.y, 0.f);
            __half2 hA = __floats2half2_rn(z0, z1);
            __half2 hB = __floats2half2_rn(z2, z3);
            A2[kc2][2 * half]     = *reinterpret_cast<unsigned int*>(&hA);
            A2[kc2][2 * half + 1] = *reinterpret_cast<unsigned int*>(&hB);
        }
    }

    // ---- matvec2: d[8 nt2][4] ----
    float d[8][4];
#pragma unroll
    for (int nt2 = 0; nt2 < 8; nt2++) {
        d[nt2][0] = d[nt2][1] = d[nt2][2] = d[nt2][3] = 0.f;
#pragma unroll
        for (int kc2 = 0; kc2 < 8; kc2++) {
            unsigned b0, b1r;
            unsigned addr = w2base + ((kc2 * 16 + krow) * 72 + nt2 * 8) * 2;
            asm volatile("ldmatrix.sync.aligned.m8n8.x2.trans.shared.b16 {%0,%1}, [%2];"
                         : "=r"(b0), "=r"(b1r) : "r"(addr));
            mma16816(d[nt2][0], d[nt2][1], d[nt2][2], d[nt2][3],
                     A2[kc2][0], A2[kc2][1], A2[kc2][2], A2[kc2][3], b0, b1r);
        }
    }

    // ---- bias + residual + h store + LN(64) epilogue ----
    int n0 = nbase + grow;
    int n1 = nbase + grow + 8;
    float sA = 0.f, sB = 0.f;
#pragma unroll
    for (int nt2 = 0; nt2 < 8; nt2++) {
        int col = nt2 * 8 + 2 * t4;
        float2 bv = *reinterpret_cast<const float2*>(b2f + col);
        d[nt2][0] += bv.x; d[nt2][1] += bv.y;
        d[nt2][2] += bv.x; d[nt2][3] += bv.y;
        if (add_residual) {
            float2 h0 = *reinterpret_cast<const float2*>(h_in + (size_t)n0 * 64 + col);
            float2 h1 = *reinterpret_cast<const float2*>(h_in + (size_t)n1 * 64 + col);
            d[nt2][0] += h0.x; d[nt2][1] += h0.y;
            d[nt2][2] += h1.x; d[nt2][3] += h1.y;
        }
        if (write_h) {
            *reinterpret_cast<float2*>(h_out + (size_t)n0 * 64 + col) = make_float2(d[nt2][0], d[nt2][1]);
            *reinterpret_cast<float2*>(h_out + (size_t)n1 * 64 + col) = make_float2(d[nt2][2], d[nt2][3]);
        }
        sA += d[nt2][0] + d[nt2][1];
        sB += d[nt2][2] + d[nt2][3];
    }
    sA += __shfl_xor_sync(0xffffffffu, sA, 1);
    sA += __shfl_xor_sync(0xffffffffu, sA, 2);
    sB += __shfl_xor_sync(0xffffffffu, sB, 1);
    sB += __shfl_xor_sync(0xffffffffu, sB, 2);
    float mA = sA * (1.f / 64.f), mB = sB * (1.f / 64.f);
    float qA = 0.f, qB = 0.f;
#pragma unroll
    for (int nt2 = 0; nt2 < 8; nt2++) {
        float e0 = d[nt2][0] - mA, e1 = d[nt2][1] - mA;
        float e2 = d[nt2][2] - mB, e3 = d[nt2][3] - mB;
        qA += e0 * e0 + e1 * e1;
        qB += e2 * e2 + e3 * e3;
    }
    qA += __shfl_xor_sync(0xffffffffu, qA, 1);
    qA += __shfl_xor_sync(0xffffffffu, qA, 2);
    qB += __shfl_xor_sync(0xffffffffu, qB, 1);
    qB += __shfl_xor_sync(0xffffffffu, qB, 2);
    float rsA = rsqrtf(qA * (1.f / 64.f) + 1e-5f);
    float rsB = rsqrtf(qB * (1.f / 64.f) + 1e-5f);

#pragma unroll
    for (int nt2 = 0; nt2 < 8; nt2++) {
        int col = nt2 * 8 + 2 * t4;
        float2 gvv = *reinterpret_cast<const float2*>(nlgf + col);
        float2 bvv = *reinterpret_cast<const float2*>(nlbf + col);
        float z0 = fmaxf((d[nt2][0] - mA) * rsA * gvv.x + bvv.x, 0.f);
        float z1 = fmaxf((d[nt2][1] - mA) * rsA * gvv.y + bvv.y, 0.f);
        float z2 = fmaxf((d[nt2][2] - mB) * rsB * gvv.x + bvv.x, 0.f);
        float z3 = fmaxf((d[nt2][3] - mB) * rsB * gvv.y + bvv.y, 0.f);
        *reinterpret_cast<float2*>(z32 + (size_t)n0 * 64 + col) = make_float2(z0, z1);
        *reinterpret_cast<float2*>(z32 + (size_t)n1 * 64 + col) = make_float2(z2, z3);
        if (z16) {
            __half2 hA = __floats2half2_rn(z0, z1);
            __half2 hB = __floats2half2_rn(z2, z3);
            *reinterpret_cast<__half2*>(z16 + (size_t)n0 * 64 + col) = hA;
            *reinterpret_cast<__half2*>(z16 + (size_t)n1 * 64 + col) = hB;
        }
    }
}

// ================= launch =================
extern "C" void kernel_launch(void* const* d_in, const int* in_sizes, int n_in,
                              void* d_out, int out_size)
{
    const float* x   = (const float*)d_in[0];
    const int*   ei  = (const int*)  d_in[1];
    const float* ea  = (const float*)d_in[2];
    const float* enw = (const float*)d_in[3];
    const float* enb = (const float*)d_in[4];
    const float* eew = (const float*)d_in[5];
    const float* eeb = (const float*)d_in[6];
    const float* lng = (const float*)d_in[7];
    const float* lnb = (const float*)d_in[8];
    const float* w1  = (const float*)d_in[9];
    const float* b1  = (const float*)d_in[10];
    const float* mg  = (const float*)d_in[11];
    const float* mb  = (const float*)d_in[12];
    const float* w2  = (const float*)d_in[13];
    const float* b2  = (const float*)d_in[14];
    const float* t   = (const float*)d_in[15];
    float* out = (float*)d_out;

    float *gh, *gz, *gdeg;
    __half *ge, *gzh, *gh16, *go16;
    int* gperm;
    cudaGetSymbolAddress((void**)&gh, g_h);
    cudaGetSymbolAddress((void**)&gz, g_z);
    cudaGetSymbolAddress((void**)&ge, g_e);
    cudaGetSymbolAddress((void**)&gzh, g_zh);
    cudaGetSymbolAddress((void**)&gh16, g_h16);
    cudaGetSymbolAddress((void**)&go16, g_o16);
    cudaGetSymbolAddress((void**)&gperm, g_perm);
    cudaGetSymbolAddress((void**)&gdeg, g_deg);

    const int smem_enc  = 4160 * 4 + 4 * 33 * 32 * 8;   // 50432 B
    const int smem_node = 56576;
    cudaFuncSetAttribute(enc_kernel,      cudaFuncAttributeMaxDynamicSharedMemorySize, smem_enc);
    cudaFuncSetAttribute(node_hmma_kernel, cudaFuncAttributeMaxDynamicSharedMemorySize, smem_node);

    const int warpNodeBlocks = (NN * 32 + 255) / 256;
    const int edgeTB         = (EE + 255) / 256;
    const int nodeHmmaBlocks = (NN / 16 + 7) / 8;       // 782

    cudaMemsetAsync(gdeg, 0, NN * sizeof(int));
    hist_kernel<<<edgeTB, 256>>>(ei);          // 1
    scan_kernel<<<1, 1024>>>();                // 2
    scatter_kernel<<<edgeTB, 256>>>(ei);       // 3

    enc_hmma_kernel<<<296, 256>>>(ea, eew, eeb, ge, gperm);                 // 4 (profiled)
    enc_kernel<<<(NN + 127) / 128, 128, smem_enc>>>(x, enw, enb, gh, gh16, NN);

    for (int i = 0; i < 4; i++) {
        const float* cin32  = (i == 0) ? gh   : gz;
        const __half* ztab  = (i == 0) ? gh16 : gzh;
        agg_kernel<<<warpNodeBlocks, 256>>>(cin32, ztab, t + i, go16);

        int last = (i == 3);
        const float* nlgp = lng + (last ? 0 : (i + 1)) * 64;
        const float* nlbp = lnb + (last ? 0 : (i + 1)) * 64;
        node_hmma_kernel<<<nodeHmmaBlocks, 256, smem_node>>>(
            go16, gh, gh,
            w1 + (size_t)i * 64 * 128, b1 + i * 128,
            mg + i * 128, mb + i * 128,
            w2 + (size_t)i * 128 * 64, b2 + i * 64,
            nlgp, nlbp,
            last ? out : gz, last ? (__half*)nullptr : gzh,
            i > 0 ? 1 : 0, last ? 0 : 1);
    }
}